// round 1
// baseline (speedup 1.0000x reference)
#include <cuda_runtime.h>
#include <math.h>

// Problem constants
#define NB 2
#define NS 1024
#define ND 512
#define NH 8
#define NP 16
#define NDH 64
#define NHP3 384
#define NCAT 2688           // 3*512 + 3*384
#define NCD 112             // 64 + 48
#define NBH 16              // NB*NH
#define NROWS 2048          // NB*NS
#define ATT_W 896           // ND + NHP3

// Scratch (static device memory; no runtime allocation)
__device__ float g_xn[NROWS * ND];
__device__ float g_Wcat[ND * NCAT];
__device__ float g_proj[NROWS * NCAT];
__device__ float g_Qc[NBH * NS * NCD];
__device__ float g_KcT[NBH * NCD * NS];
__device__ float g_Vc[NBH * NS * NCD];
__device__ float g_qn2[NBH * NS];
__device__ float g_kn2[NBH * NS];
__device__ float g_bias[(size_t)NBH * NS * NS];   // 64 MB
__device__ float g_T[(size_t)NBH * NS * NS];      // 64 MB
__device__ float g_att[NROWS * ATT_W];
__device__ float g_pre[NROWS * ND];

// ---------------- LayerNorm (optionally with residual add) ----------------
__global__ void k_ln(const float* __restrict__ x, const float* __restrict__ res,
                     const float* __restrict__ g, const float* __restrict__ b,
                     float* __restrict__ y) {
    int row = blockIdx.x, tid = threadIdx.x;
    const float* xr = x + (size_t)row * ND;
    float v0 = xr[tid], v1 = xr[tid + 256];
    if (res) {
        v0 += res[(size_t)row * ND + tid];
        v1 += res[(size_t)row * ND + tid + 256];
    }
    __shared__ float red[256];
    red[tid] = v0 + v1;
    __syncthreads();
    for (int s = 128; s > 0; s >>= 1) { if (tid < s) red[tid] += red[tid + s]; __syncthreads(); }
    float mean = red[0] * (1.0f / ND);
    __syncthreads();
    float d0 = v0 - mean, d1 = v1 - mean;
    red[tid] = d0 * d0 + d1 * d1;
    __syncthreads();
    for (int s = 128; s > 0; s >>= 1) { if (tid < s) red[tid] += red[tid + s]; __syncthreads(); }
    float rstd = rsqrtf(red[0] * (1.0f / ND) + 1e-5f);
    float* yr = y + (size_t)row * ND;
    yr[tid]       = d0 * rstd * g[tid] + b[tid];
    yr[tid + 256] = d1 * rstd * g[tid + 256] + b[tid + 256];
}

// ---------------- Concatenate projection weights into [512 x 2688] ----------------
__global__ void k_wcat(const float* __restrict__ Wq, const float* __restrict__ Wk,
                       const float* __restrict__ Wv, const float* __restrict__ Wqp,
                       const float* __restrict__ Wkp, const float* __restrict__ Wvp) {
    int idx = blockIdx.x * 256 + threadIdx.x;
    if (idx >= ND * NCAT) return;
    int k = idx / NCAT, c = idx % NCAT;
    float v;
    if      (c < 512)  v = Wq[k * 512 + c];
    else if (c < 1024) v = Wk[k * 512 + (c - 512)];
    else if (c < 1536) v = Wv[k * 512 + (c - 1024)];
    else if (c < 1920) v = Wqp[k * 384 + (c - 1536)];
    else if (c < 2304) v = Wkp[k * 384 + (c - 1920)];
    else               v = Wvp[k * 384 + (c - 2304)];
    g_Wcat[idx] = v;
}

// ---------------- Generic SGEMM: C = A[MxK] @ B[KxN] (+ bias) ----------------
// BM=BN=64, BK=16, 256 threads, 4x4 per thread. K must be a multiple of 16.
__global__ void k_sgemm(int M, int N, int K,
                        const float* __restrict__ A, const float* __restrict__ B,
                        const float* __restrict__ bias, float* __restrict__ C) {
    __shared__ float As[16][64];
    __shared__ float Bs[16][64];
    int tid = threadIdx.x;
    int trow = tid >> 4, tcol = tid & 15;
    int rb = blockIdx.y * 64, cb = blockIdx.x * 64;
    float acc[4][4] = {};
    for (int k0 = 0; k0 < K; k0 += 16) {
#pragma unroll
        for (int i = 0; i < 4; i++) {
            int idx = tid + i * 256; int r = idx >> 4, c = idx & 15;
            As[c][r] = (rb + r < M) ? A[(size_t)(rb + r) * K + k0 + c] : 0.0f;
        }
#pragma unroll
        for (int i = 0; i < 4; i++) {
            int idx = tid + i * 256; int r = idx >> 6, c = idx & 63;
            Bs[r][c] = (cb + c < N) ? B[(size_t)(k0 + r) * N + cb + c] : 0.0f;
        }
        __syncthreads();
#pragma unroll
        for (int kk = 0; kk < 16; kk++) {
            float a[4], bv[4];
#pragma unroll
            for (int i = 0; i < 4; i++) a[i] = As[kk][trow * 4 + i];
#pragma unroll
            for (int j = 0; j < 4; j++) bv[j] = Bs[kk][tcol * 4 + j];
#pragma unroll
            for (int i = 0; i < 4; i++)
#pragma unroll
                for (int j = 0; j < 4; j++) acc[i][j] = fmaf(a[i], bv[j], acc[i][j]);
        }
        __syncthreads();
    }
#pragma unroll
    for (int i = 0; i < 4; i++) {
        int r = rb + trow * 4 + i; if (r >= M) continue;
#pragma unroll
        for (int j = 0; j < 4; j++) {
            int c = cb + tcol * 4 + j; if (c >= N) continue;
            float v = acc[i][j];
            if (bias) v += bias[c];
            C[(size_t)r * N + c] = v;
        }
    }
}

// ---------------- Rearrange: build Qc/KcT/Vc + qn2/kn2 ----------------
__global__ void k_rearrange(const float* __restrict__ coords,
                            const float* __restrict__ bqp, const float* __restrict__ bkp,
                            const float* __restrict__ bvp) {
    int row = blockIdx.x;              // 0..2047 = b*1024+s
    int b = row >> 10, s = row & 1023;
    int j = threadIdx.x;               // 0..127
    __shared__ float sq[128], sk[128];
    const float* pr = g_proj + (size_t)row * NCAT;
    for (int h = 0; h < NH; h++) {
        int bh = b * NH + h;
        float qv = 0.f, kv = 0.f, vv = 0.f, q2 = 0.f, k2 = 0.f;
        if (j < 64) {
            qv = pr[h * 64 + j] * 0.125f;     // SCALE = DH^-0.5 = 1/8
            kv = pr[512 + h * 64 + j];
            vv = pr[1024 + h * 64 + j];
        } else if (j < NCD) {
            int jj = j - 64; int c = jj % 3;
            float ce = coords[(size_t)row * 3 + c];
            qv = pr[1536 + h * 48 + jj] + bqp[h * 48 + jj] + ce;
            kv = pr[1920 + h * 48 + jj] + bkp[h * 48 + jj] + ce;
            vv = pr[2304 + h * 48 + jj] + bvp[h * 48 + jj];
            q2 = qv * qv; k2 = kv * kv;
        }
        if (j < NCD) {
            g_Qc[((size_t)bh * NS + s) * NCD + j] = qv;
            g_KcT[((size_t)bh * NCD + j) * NS + s] = kv;
            g_Vc[((size_t)bh * NS + s) * NCD + j] = vv;
        }
        sq[j] = q2; sk[j] = k2;
        __syncthreads();
        for (int st = 64; st > 0; st >>= 1) {
            if (j < st) { sq[j] += sq[j + st]; sk[j] += sk[j + st]; }
            __syncthreads();
        }
        if (j == 0) { g_qn2[bh * NS + s] = sq[0]; g_kn2[bh * NS + s] = sk[0]; }
        __syncthreads();
    }
}

// ---------------- Distance-MLP bias plane (masked, incl. -0.5(qn2+kn2)) ----------------
__global__ void k_bias(const float* __restrict__ coords,
                       const float* __restrict__ Wd1, const float* __restrict__ bd1,
                       const float* __restrict__ Wd2, const float* __restrict__ bd2) {
    int q = blockIdx.x, b = blockIdx.y, tid = threadIdx.x;
    __shared__ float w1[32], c1[32], w2[256], c2[8];
    if (tid < 32) { w1[tid] = Wd1[tid]; c1[tid] = bd1[tid]; }
    if (tid < 8)  c2[tid] = bd2[tid];
    w2[tid] = Wd2[tid];   // 32*8 = 256 exactly
    __syncthreads();
    float cqx = coords[((size_t)b * NS + q) * 3 + 0];
    float cqy = coords[((size_t)b * NS + q) * 3 + 1];
    float cqz = coords[((size_t)b * NS + q) * 3 + 2];
    float qn2v[8];
#pragma unroll
    for (int h = 0; h < 8; h++) qn2v[h] = g_qn2[(b * 8 + h) * NS + q];
    for (int k = tid; k < NS; k += 256) {
        float dx = cqx - coords[((size_t)b * NS + k) * 3 + 0];
        float dy = cqy - coords[((size_t)b * NS + k) * 3 + 1];
        float dz = cqz - coords[((size_t)b * NS + k) * 3 + 2];
        float dist = sqrtf(dx * dx + dy * dy + dz * dz);
        if (dist < 15.0f) {
            float hb[8];
#pragma unroll
            for (int h = 0; h < 8; h++) hb[h] = c2[h];
#pragma unroll
            for (int jj = 0; jj < 32; jj++) {
                float hv = fmaxf(fmaf(dist, w1[jj], c1[jj]), 0.0f);
#pragma unroll
                for (int h = 0; h < 8; h++) hb[h] = fmaf(hv, w2[jj * 8 + h], hb[h]);
            }
#pragma unroll
            for (int h = 0; h < 8; h++) {
                int bh = b * 8 + h;
                g_bias[((size_t)bh * NS + q) * NS + k] =
                    hb[h] - 0.5f * (qn2v[h] + g_kn2[bh * NS + k]);
            }
        } else {
#pragma unroll
            for (int h = 0; h < 8; h++) {
                int bh = b * 8 + h;
                g_bias[((size_t)bh * NS + q) * NS + k] = -1e30f;
            }
        }
    }
}

// ---------------- Logits GEMM: T = Qc @ KcT + bias (per b,h) ----------------
__global__ void k_logits() {
    int bh = blockIdx.z;
    const float* A    = g_Qc   + (size_t)bh * NS * NCD;
    const float* Bm   = g_KcT  + (size_t)bh * NCD * NS;
    const float* bias = g_bias + (size_t)bh * NS * NS;
    float* C          = g_T    + (size_t)bh * NS * NS;
    __shared__ float As[16][64];
    __shared__ float Bs[16][64];
    int tid = threadIdx.x;
    int trow = tid >> 4, tcol = tid & 15;
    int rb = blockIdx.y * 64, cb = blockIdx.x * 64;
    float acc[4][4] = {};
    for (int k0 = 0; k0 < NCD; k0 += 16) {   // 112 = 7*16
#pragma unroll
        for (int i = 0; i < 4; i++) {
            int idx = tid + i * 256; int r = idx >> 4, c = idx & 15;
            As[c][r] = A[(size_t)(rb + r) * NCD + k0 + c];
        }
#pragma unroll
        for (int i = 0; i < 4; i++) {
            int idx = tid + i * 256; int r = idx >> 6, c = idx & 63;
            Bs[r][c] = Bm[(size_t)(k0 + r) * NS + cb + c];
        }
        __syncthreads();
#pragma unroll
        for (int kk = 0; kk < 16; kk++) {
            float a[4], bv[4];
#pragma unroll
            for (int i = 0; i < 4; i++) a[i] = As[kk][trow * 4 + i];
#pragma unroll
            for (int j = 0; j < 4; j++) bv[j] = Bs[kk][tcol * 4 + j];
#pragma unroll
            for (int i = 0; i < 4; i++)
#pragma unroll
                for (int j = 0; j < 4; j++) acc[i][j] = fmaf(a[i], bv[j], acc[i][j]);
        }
        __syncthreads();
    }
#pragma unroll
    for (int i = 0; i < 4; i++) {
        int r = rb + trow * 4 + i;
#pragma unroll
        for (int j = 0; j < 4; j++) {
            int c = cb + tcol * 4 + j;
            float bv = bias[(size_t)r * NS + c];
            C[(size_t)r * NS + c] = (bv < -1e20f) ? -1e9f : acc[i][j] + bv;
        }
    }
}

// ---------------- Softmax over k (in place on g_T) ----------------
__global__ void k_softmax() {
    float* p = g_T + (size_t)blockIdx.x * NS;
    int tid = threadIdx.x;
    float v[4];
#pragma unroll
    for (int i = 0; i < 4; i++) v[i] = p[tid + i * 256];
    float m = fmaxf(fmaxf(v[0], v[1]), fmaxf(v[2], v[3]));
    __shared__ float red[256];
    red[tid] = m; __syncthreads();
    for (int s = 128; s > 0; s >>= 1) { if (tid < s) red[tid] = fmaxf(red[tid], red[tid + s]); __syncthreads(); }
    m = red[0];
    __syncthreads();
    float sum = 0.f;
#pragma unroll
    for (int i = 0; i < 4; i++) { v[i] = __expf(v[i] - m); sum += v[i]; }
    red[tid] = sum; __syncthreads();
    for (int s = 128; s > 0; s >>= 1) { if (tid < s) red[tid] += red[tid + s]; __syncthreads(); }
    float inv = 1.0f / red[0];
#pragma unroll
    for (int i = 0; i < 4; i++) p[tid + i * 256] = v[i] * inv;
}

// ---------------- AV GEMM: [af|ap] = W @ Vc, scattered into concat layout ----------------
__global__ void k_av() {
    int bh = blockIdx.z, b = bh >> 3, h = bh & 7;
    const float* A  = g_T  + (size_t)bh * NS * NS;
    const float* Bm = g_Vc + (size_t)bh * NS * NCD;
    __shared__ float As[16][64];
    __shared__ float Bs[16][64];
    int tid = threadIdx.x;
    int trow = tid >> 4, tcol = tid & 15;
    int rb = blockIdx.y * 64, cb = blockIdx.x * 64;
    float acc[4][4] = {};
    for (int k0 = 0; k0 < NS; k0 += 16) {
#pragma unroll
        for (int i = 0; i < 4; i++) {
            int idx = tid + i * 256; int r = idx >> 4, c = idx & 15;
            As[c][r] = A[(size_t)(rb + r) * NS + k0 + c];
        }
#pragma unroll
        for (int i = 0; i < 4; i++) {
            int idx = tid + i * 256; int r = idx >> 6, c = idx & 63;
            Bs[r][c] = (cb + c < NCD) ? Bm[(size_t)(k0 + r) * NCD + cb + c] : 0.0f;
        }
        __syncthreads();
#pragma unroll
        for (int kk = 0; kk < 16; kk++) {
            float a[4], bv[4];
#pragma unroll
            for (int i = 0; i < 4; i++) a[i] = As[kk][trow * 4 + i];
#pragma unroll
            for (int j = 0; j < 4; j++) bv[j] = Bs[kk][tcol * 4 + j];
#pragma unroll
            for (int i = 0; i < 4; i++)
#pragma unroll
                for (int j = 0; j < 4; j++) acc[i][j] = fmaf(a[i], bv[j], acc[i][j]);
        }
        __syncthreads();
    }
#pragma unroll
    for (int i = 0; i < 4; i++) {
        int q = rb + trow * 4 + i;
#pragma unroll
        for (int j = 0; j < 4; j++) {
            int c = cb + tcol * 4 + j;
            if (c >= NCD) continue;
            int col = (c < 64) ? (h * 64 + c) : (512 + h * 48 + (c - 64));
            g_att[(size_t)(b * NS + q) * ATT_W + col] = acc[i][j];
        }
    }
}

// ---------------- Coords update ----------------
__global__ void k_coords(const float* __restrict__ coords, float* __restrict__ outc) {
    int idx = blockIdx.x * 256 + threadIdx.x;
    if (idx >= NROWS * 3) return;
    int row = idx / 3, c = idx % 3;
    const float* ap = g_att + (size_t)row * ATT_W + 512;
    float s = 0.f;
#pragma unroll 8
    for (int t = 0; t < 128; t++) s += ap[t * 3 + c];
    outc[idx] = coords[idx] + 0.1f * s * (1.0f / 128.0f);
}

// ---------------- Launch ----------------
extern "C" void kernel_launch(void* const* d_in, const int* in_sizes, int n_in,
                              void* d_out, int out_size) {
    const float* x      = (const float*)d_in[0];
    const float* coords = (const float*)d_in[1];
    const float* Wq     = (const float*)d_in[2];
    const float* Wk     = (const float*)d_in[3];
    const float* Wv     = (const float*)d_in[4];
    const float* Wqp    = (const float*)d_in[5];
    const float* bqp    = (const float*)d_in[6];
    const float* Wkp    = (const float*)d_in[7];
    const float* bkp    = (const float*)d_in[8];
    const float* Wvp    = (const float*)d_in[9];
    const float* bvp    = (const float*)d_in[10];
    const float* Wd1    = (const float*)d_in[11];
    const float* bd1    = (const float*)d_in[12];
    const float* Wd2    = (const float*)d_in[13];
    const float* bd2    = (const float*)d_in[14];
    const float* Wo     = (const float*)d_in[15];
    const float* bo     = (const float*)d_in[16];
    const float* g1     = (const float*)d_in[17];
    const float* b1     = (const float*)d_in[18];
    const float* g2     = (const float*)d_in[19];
    const float* b2     = (const float*)d_in[20];
    float* out = (float*)d_out;

    float *p_xn, *p_wcat, *p_proj, *p_att, *p_pre;
    cudaGetSymbolAddress((void**)&p_xn,   g_xn);
    cudaGetSymbolAddress((void**)&p_wcat, g_Wcat);
    cudaGetSymbolAddress((void**)&p_proj, g_proj);
    cudaGetSymbolAddress((void**)&p_att,  g_att);
    cudaGetSymbolAddress((void**)&p_pre,  g_pre);

    // 1. LayerNorm
    k_ln<<<NROWS, 256>>>(x, nullptr, g1, b1, p_xn);
    // 2. Concatenated projection weights + fused projection GEMM
    k_wcat<<<(ND * NCAT + 255) / 256, 256>>>(Wq, Wk, Wv, Wqp, Wkp, Wvp);
    k_sgemm<<<dim3(NCAT / 64, NROWS / 64), 256>>>(NROWS, NCAT, ND, p_xn, p_wcat, nullptr, p_proj);
    // 3. Rearrange into per-(b,h) concat Q/K/V + point norms
    k_rearrange<<<NROWS, 128>>>(coords, bqp, bkp, bvp);
    // 4. Distance-MLP bias plane with mask + norm terms
    k_bias<<<dim3(NS, NB), 256>>>(coords, Wd1, bd1, Wd2, bd2);
    // 5. Logits GEMM (attn + point dot fused, K=112)
    k_logits<<<dim3(NS / 64, NS / 64, NBH), 256>>>();
    // 6. Softmax
    k_softmax<<<NBH * NS, 256>>>();
    // 7. AV GEMM (feature + point values fused, N=112)
    k_av<<<dim3(2, NS / 64, NBH), 256>>>();
    // 8. Output projection
    k_sgemm<<<dim3(ND / 64, NROWS / 64), 256>>>(NROWS, ND, ATT_W, p_att, Wo, bo, p_pre);
    // 9. Residual + final LayerNorm -> out
    k_ln<<<NROWS, 256>>>(x, p_pre, g2, b2, out);
    // 10. Coords update -> second output
    k_coords<<<(NROWS * 3 + 255) / 256, 256>>>(coords, out + (size_t)NROWS * ND);
}

// round 2
// speedup vs baseline: 1.2236x; 1.2236x over previous
#include <cuda_runtime.h>
#include <math.h>

// Problem constants
#define NB 2
#define NS 1024
#define ND 512
#define NH 8
#define NCAT 2688           // 3*512 + 3*384
#define NCD 112             // 64 + 48
#define NBH 16              // NB*NH
#define NROWS 2048          // NB*NS
#define ATT_W 896           // ND + NHP3

// Scratch (static device memory; no runtime allocation)
__device__ float g_xn[NROWS * ND];
__device__ float g_Wcat[ND * NCAT];
__device__ float g_proj[NROWS * NCAT];
__device__ float g_Qc[NBH * NS * NCD];
__device__ float g_Kc[NBH * NS * NCD];
__device__ float g_Vc[NBH * NS * NCD];
__device__ float g_qn2[NBH * NS];
__device__ float g_kn2[NBH * NS];
__device__ float g_bias[(size_t)NBH * NS * NS];   // 64 MB
__device__ float g_T[(size_t)NBH * NS * NS];      // 64 MB
__device__ float g_att[NROWS * ATT_W];
__device__ float g_pre[NROWS * ND];

// ---------------- f32x2 packed-FMA helpers (FFMA2; ptxas won't auto-fuse) ----------------
__device__ __forceinline__ unsigned long long dup2(float x) {
    unsigned long long r; unsigned u = __float_as_uint(x);
    asm("mov.b64 %0, {%1, %1};" : "=l"(r) : "r"(u));
    return r;
}
__device__ __forceinline__ void ffma2(unsigned long long& c, unsigned long long a, unsigned long long b) {
    asm("fma.rn.f32x2 %0, %1, %2, %0;" : "+l"(c) : "l"(a), "l"(b));
}
__device__ __forceinline__ void unpk(unsigned long long v, float& lo, float& hi) {
    unsigned a, b;
    asm("mov.b64 {%0, %1}, %2;" : "=r"(a), "=r"(b) : "l"(v));
    lo = __uint_as_float(a); hi = __uint_as_float(b);
}

// ---------------- LayerNorm (optionally with residual add) ----------------
__global__ void k_ln(const float* __restrict__ x, const float* __restrict__ res,
                     const float* __restrict__ g, const float* __restrict__ b,
                     float* __restrict__ y) {
    int row = blockIdx.x, tid = threadIdx.x;
    const float* xr = x + (size_t)row * ND;
    float v0 = xr[tid], v1 = xr[tid + 256];
    if (res) {
        v0 += res[(size_t)row * ND + tid];
        v1 += res[(size_t)row * ND + tid + 256];
    }
    __shared__ float red[256];
    red[tid] = v0 + v1;
    __syncthreads();
    for (int s = 128; s > 0; s >>= 1) { if (tid < s) red[tid] += red[tid + s]; __syncthreads(); }
    float mean = red[0] * (1.0f / ND);
    __syncthreads();
    float d0 = v0 - mean, d1 = v1 - mean;
    red[tid] = d0 * d0 + d1 * d1;
    __syncthreads();
    for (int s = 128; s > 0; s >>= 1) { if (tid < s) red[tid] += red[tid + s]; __syncthreads(); }
    float rstd = rsqrtf(red[0] * (1.0f / ND) + 1e-5f);
    float* yr = y + (size_t)row * ND;
    yr[tid]       = d0 * rstd * g[tid] + b[tid];
    yr[tid + 256] = d1 * rstd * g[tid + 256] + b[tid + 256];
}

// ---------------- Concatenate projection weights into [512 x 2688] ----------------
__global__ void k_wcat(const float* __restrict__ Wq, const float* __restrict__ Wk,
                       const float* __restrict__ Wv, const float* __restrict__ Wqp,
                       const float* __restrict__ Wkp, const float* __restrict__ Wvp) {
    int idx = blockIdx.x * 256 + threadIdx.x;
    if (idx >= ND * NCAT) return;
    int k = idx / NCAT, c = idx % NCAT;
    float v;
    if      (c < 512)  v = Wq[k * 512 + c];
    else if (c < 1024) v = Wk[k * 512 + (c - 512)];
    else if (c < 1536) v = Wv[k * 512 + (c - 1024)];
    else if (c < 1920) v = Wqp[k * 384 + (c - 1536)];
    else if (c < 2304) v = Wkp[k * 384 + (c - 1920)];
    else               v = Wvp[k * 384 + (c - 2304)];
    g_Wcat[idx] = v;
}

// ---------------- NN SGEMM: C = A[MxK] @ B[KxN] (+ bias). BMxBN tile, f32x2 FMA ----------
// BM = TM*16, BN = 128, BK = 16, 256 threads, TMx8 per thread, double buffered.
// Requires: M % BM == 0, K % 16 == 0. N guarded.
template<int TM>
__global__ void __launch_bounds__(256, 2)
gemm_nn(int M, int N, int K,
        const float* __restrict__ A, const float* __restrict__ B,
        const float* __restrict__ bias, float* __restrict__ C)
{
    constexpr int BM = TM * 16;
    constexpr int AP = BM + 4;
    constexpr int LA = BM / 64;       // float4 A-loads per thread
    __shared__ float As[2][16][AP];   // [k][m], transposed store
    __shared__ float Bs[2][16][128];  // [k][n]
    const int tid = threadIdx.x;
    const int tn = tid & 15, tm = tid >> 4;
    const int m0 = tm * TM, n0 = tn * 8;
    const int rb = blockIdx.y * BM, cb = blockIdx.x * 128;

    unsigned long long acc[TM][4];
#pragma unroll
    for (int i = 0; i < TM; i++)
#pragma unroll
        for (int j = 0; j < 4; j++) acc[i][j] = 0ull;

    int aR[LA], aC[LA];
#pragma unroll
    for (int i = 0; i < LA; i++) { int idx = tid + i * 256; aR[i] = idx >> 2; aC[i] = (idx & 3) * 4; }
    int bR[2], bC[2];
#pragma unroll
    for (int i = 0; i < 2; i++)  { int idx = tid + i * 256; bR[i] = idx >> 5; bC[i] = (idx & 31) * 4; }

    float4 av[LA], bv[2];
#pragma unroll
    for (int i = 0; i < LA; i++)
        av[i] = *(const float4*)(A + (size_t)(rb + aR[i]) * K + aC[i]);
#pragma unroll
    for (int i = 0; i < 2; i++) {
        int col = cb + bC[i];
        bv[i] = (col < N) ? *(const float4*)(B + (size_t)bR[i] * N + col)
                          : make_float4(0.f, 0.f, 0.f, 0.f);
    }
#pragma unroll
    for (int i = 0; i < LA; i++) {
        As[0][aC[i] + 0][aR[i]] = av[i].x;
        As[0][aC[i] + 1][aR[i]] = av[i].y;
        As[0][aC[i] + 2][aR[i]] = av[i].z;
        As[0][aC[i] + 3][aR[i]] = av[i].w;
    }
#pragma unroll
    for (int i = 0; i < 2; i++)
        *(float4*)&Bs[0][bR[i]][bC[i]] = bv[i];
    __syncthreads();

    int buf = 0;
    for (int k0 = 0; k0 < K; k0 += 16) {
        const bool nxt = (k0 + 16) < K;
        if (nxt) {
#pragma unroll
            for (int i = 0; i < LA; i++)
                av[i] = *(const float4*)(A + (size_t)(rb + aR[i]) * K + k0 + 16 + aC[i]);
#pragma unroll
            for (int i = 0; i < 2; i++) {
                int col = cb + bC[i];
                bv[i] = (col < N) ? *(const float4*)(B + (size_t)(k0 + 16 + bR[i]) * N + col)
                                  : make_float4(0.f, 0.f, 0.f, 0.f);
            }
        }
#pragma unroll
        for (int kk = 0; kk < 16; kk++) {
            unsigned long long bb[4], ad[TM];
#pragma unroll
            for (int j = 0; j < 4; j++)
                bb[j] = *(const unsigned long long*)&Bs[buf][kk][n0 + 2 * j];
#pragma unroll
            for (int i = 0; i < TM; i++)
                ad[i] = dup2(As[buf][kk][m0 + i]);
#pragma unroll
            for (int i = 0; i < TM; i++)
#pragma unroll
                for (int j = 0; j < 4; j++)
                    ffma2(acc[i][j], ad[i], bb[j]);
        }
        if (nxt) {
            int nb = buf ^ 1;
#pragma unroll
            for (int i = 0; i < LA; i++) {
                As[nb][aC[i] + 0][aR[i]] = av[i].x;
                As[nb][aC[i] + 1][aR[i]] = av[i].y;
                As[nb][aC[i] + 2][aR[i]] = av[i].z;
                As[nb][aC[i] + 3][aR[i]] = av[i].w;
            }
#pragma unroll
            for (int i = 0; i < 2; i++)
                *(float4*)&Bs[nb][bR[i]][bC[i]] = bv[i];
            __syncthreads();
            buf = nb;
        }
    }

#pragma unroll
    for (int i = 0; i < TM; i++) {
        int r = rb + m0 + i;
#pragma unroll
        for (int j = 0; j < 4; j++) {
            int c = cb + n0 + 2 * j;
            if (c >= N) continue;
            float lo, hi; unpk(acc[i][j], lo, hi);
            if (bias) { lo += bias[c]; hi += bias[c + 1]; }
            C[(size_t)r * N + c]     = lo;
            C[(size_t)r * N + c + 1] = hi;
        }
    }
}

// ---------------- Logits: T = Qc @ Kc^T + bias (NT, per b,h; M=N=1024, K=112) ------------
__global__ void __launch_bounds__(256, 2) k_logits() {
    const int bh = blockIdx.z;
    const float* A    = g_Qc   + (size_t)bh * NS * NCD;
    const float* Bk   = g_Kc   + (size_t)bh * NS * NCD;
    const float* bias = g_bias + (size_t)bh * NS * NS;
    float* C          = g_T    + (size_t)bh * NS * NS;
    __shared__ float As[2][16][132];
    __shared__ float Bs[2][16][132];
    const int tid = threadIdx.x;
    const int tn = tid & 15, tm = tid >> 4;
    const int m0 = tm * 8, n0 = tn * 8;
    const int rb = blockIdx.y * 128, cb = blockIdx.x * 128;

    unsigned long long acc[8][4];
#pragma unroll
    for (int i = 0; i < 8; i++)
#pragma unroll
        for (int j = 0; j < 4; j++) acc[i][j] = 0ull;

    const int R = tid >> 2, Cc = (tid & 3) * 4;
    float4 av[2], bv[2];
#pragma unroll
    for (int i = 0; i < 2; i++) {
        av[i] = *(const float4*)(A  + (size_t)(rb + R + i * 64) * NCD + Cc);
        bv[i] = *(const float4*)(Bk + (size_t)(cb + R + i * 64) * NCD + Cc);
    }
#pragma unroll
    for (int i = 0; i < 2; i++) {
        As[0][Cc + 0][R + i * 64] = av[i].x; As[0][Cc + 1][R + i * 64] = av[i].y;
        As[0][Cc + 2][R + i * 64] = av[i].z; As[0][Cc + 3][R + i * 64] = av[i].w;
        Bs[0][Cc + 0][R + i * 64] = bv[i].x; Bs[0][Cc + 1][R + i * 64] = bv[i].y;
        Bs[0][Cc + 2][R + i * 64] = bv[i].z; Bs[0][Cc + 3][R + i * 64] = bv[i].w;
    }
    __syncthreads();

    int buf = 0;
    for (int k0 = 0; k0 < NCD; k0 += 16) {   // 7 iters
        const bool nxt = (k0 + 16) < NCD;
        if (nxt) {
#pragma unroll
            for (int i = 0; i < 2; i++) {
                av[i] = *(const float4*)(A  + (size_t)(rb + R + i * 64) * NCD + k0 + 16 + Cc);
                bv[i] = *(const float4*)(Bk + (size_t)(cb + R + i * 64) * NCD + k0 + 16 + Cc);
            }
        }
#pragma unroll
        for (int kk = 0; kk < 16; kk++) {
            unsigned long long bb[4], ad[8];
#pragma unroll
            for (int j = 0; j < 4; j++)
                bb[j] = *(const unsigned long long*)&Bs[buf][kk][n0 + 2 * j];
#pragma unroll
            for (int i = 0; i < 8; i++)
                ad[i] = dup2(As[buf][kk][m0 + i]);
#pragma unroll
            for (int i = 0; i < 8; i++)
#pragma unroll
                for (int j = 0; j < 4; j++)
                    ffma2(acc[i][j], ad[i], bb[j]);
        }
        if (nxt) {
            int nb = buf ^ 1;
#pragma unroll
            for (int i = 0; i < 2; i++) {
                As[nb][Cc + 0][R + i * 64] = av[i].x; As[nb][Cc + 1][R + i * 64] = av[i].y;
                As[nb][Cc + 2][R + i * 64] = av[i].z; As[nb][Cc + 3][R + i * 64] = av[i].w;
                Bs[nb][Cc + 0][R + i * 64] = bv[i].x; Bs[nb][Cc + 1][R + i * 64] = bv[i].y;
                Bs[nb][Cc + 2][R + i * 64] = bv[i].z; Bs[nb][Cc + 3][R + i * 64] = bv[i].w;
            }
            __syncthreads();
            buf = nb;
        }
    }

#pragma unroll
    for (int i = 0; i < 8; i++) {
        int r = rb + m0 + i;
#pragma unroll
        for (int j = 0; j < 4; j++) {
            int c = cb + n0 + 2 * j;
            float lo, hi; unpk(acc[i][j], lo, hi);
            float b0 = bias[(size_t)r * NS + c];
            float b1 = bias[(size_t)r * NS + c + 1];
            C[(size_t)r * NS + c]     = (b0 < -1e20f) ? -1e9f : lo + b0;
            C[(size_t)r * NS + c + 1] = (b1 < -1e20f) ? -1e9f : hi + b1;
        }
    }
}

// ---------------- AV: [af|ap] = W @ Vc (NN, M=1024, N=112, K=1024), scatter epilogue -----
__global__ void __launch_bounds__(256, 2) k_av() {
    const int bh = blockIdx.z, b = bh >> 3, h = bh & 7;
    const float* A  = g_T  + (size_t)bh * NS * NS;
    const float* Bm = g_Vc + (size_t)bh * NS * NCD;
    __shared__ float As[2][16][132];
    __shared__ float Bs[2][16][128];
    const int tid = threadIdx.x;
    const int tn = tid & 15, tm = tid >> 4;
    const int m0 = tm * 8, n0 = tn * 8;
    const int rb = blockIdx.y * 128;

    unsigned long long acc[8][4];
#pragma unroll
    for (int i = 0; i < 8; i++)
#pragma unroll
        for (int j = 0; j < 4; j++) acc[i][j] = 0ull;

    const int aRb = tid >> 2, aCb = (tid & 3) * 4;
    const int bRb = tid >> 5, bCb = (tid & 31) * 4;
    float4 av[2], bv[2];
#pragma unroll
    for (int i = 0; i < 2; i++) {
        av[i] = *(const float4*)(A + (size_t)(rb + aRb + i * 64) * NS + aCb);
        bv[i] = (bCb < NCD) ? *(const float4*)(Bm + (size_t)(bRb + i * 8) * NCD + bCb)
                            : make_float4(0.f, 0.f, 0.f, 0.f);
    }
#pragma unroll
    for (int i = 0; i < 2; i++) {
        As[0][aCb + 0][aRb + i * 64] = av[i].x; As[0][aCb + 1][aRb + i * 64] = av[i].y;
        As[0][aCb + 2][aRb + i * 64] = av[i].z; As[0][aCb + 3][aRb + i * 64] = av[i].w;
        *(float4*)&Bs[0][bRb + i * 8][bCb] = bv[i];
    }
    __syncthreads();

    int buf = 0;
    for (int k0 = 0; k0 < NS; k0 += 16) {
        const bool nxt = (k0 + 16) < NS;
        if (nxt) {
#pragma unroll
            for (int i = 0; i < 2; i++) {
                av[i] = *(const float4*)(A + (size_t)(rb + aRb + i * 64) * NS + k0 + 16 + aCb);
                bv[i] = (bCb < NCD) ? *(const float4*)(Bm + (size_t)(k0 + 16 + bRb + i * 8) * NCD + bCb)
                                    : make_float4(0.f, 0.f, 0.f, 0.f);
            }
        }
#pragma unroll
        for (int kk = 0; kk < 16; kk++) {
            unsigned long long bb[4], ad[8];
#pragma unroll
            for (int j = 0; j < 4; j++)
                bb[j] = *(const unsigned long long*)&Bs[buf][kk][n0 + 2 * j];
#pragma unroll
            for (int i = 0; i < 8; i++)
                ad[i] = dup2(As[buf][kk][m0 + i]);
#pragma unroll
            for (int i = 0; i < 8; i++)
#pragma unroll
                for (int j = 0; j < 4; j++)
                    ffma2(acc[i][j], ad[i], bb[j]);
        }
        if (nxt) {
            int nb = buf ^ 1;
#pragma unroll
            for (int i = 0; i < 2; i++) {
                As[nb][aCb + 0][aRb + i * 64] = av[i].x; As[nb][aCb + 1][aRb + i * 64] = av[i].y;
                As[nb][aCb + 2][aRb + i * 64] = av[i].z; As[nb][aCb + 3][aRb + i * 64] = av[i].w;
                *(float4*)&Bs[nb][bRb + i * 8][bCb] = bv[i];
            }
            __syncthreads();
            buf = nb;
        }
    }

#pragma unroll
    for (int i = 0; i < 8; i++) {
        int q = rb + m0 + i;
#pragma unroll
        for (int j = 0; j < 4; j++) {
            int c = n0 + 2 * j;
            if (c >= NCD) continue;
            float lo, hi; unpk(acc[i][j], lo, hi);
            int col0 = (c < 64)     ? (h * 64 + c)     : (512 + h * 48 + (c - 64));
            int col1 = (c + 1 < 64) ? (h * 64 + c + 1) : (512 + h * 48 + (c + 1 - 64));
            size_t base = (size_t)(b * NS + q) * ATT_W;
            g_att[base + col0] = lo;
            g_att[base + col1] = hi;
        }
    }
}

// ---------------- Rearrange: build Qc/Kc/Vc rows (all coalesced) ----------------
__global__ void k_rearrange(const float* __restrict__ coords,
                            const float* __restrict__ bqp, const float* __restrict__ bkp,
                            const float* __restrict__ bvp) {
    int row = blockIdx.x;              // b*1024+s
    int b = row >> 10, s = row & 1023;
    int j = threadIdx.x;               // 0..127
    if (j >= NCD) return;
    const float* pr = g_proj + (size_t)row * NCAT;
    float ce = 0.f; int jj = 0;
    if (j >= 64) { jj = j - 64; ce = coords[(size_t)row * 3 + (jj % 3)]; }
#pragma unroll
    for (int h = 0; h < NH; h++) {
        size_t o = ((size_t)(b * NH + h) * NS + s) * NCD + j;
        if (j < 64) {
            g_Qc[o] = pr[h * 64 + j] * 0.125f;     // SCALE = 1/8
            g_Kc[o] = pr[512 + h * 64 + j];
            g_Vc[o] = pr[1024 + h * 64 + j];
        } else {
            g_Qc[o] = pr[1536 + h * 48 + jj] + bqp[h * 48 + jj] + ce;
            g_Kc[o] = pr[1920 + h * 48 + jj] + bkp[h * 48 + jj] + ce;
            g_Vc[o] = pr[2304 + h * 48 + jj] + bvp[h * 48 + jj];
        }
    }
}

// ---------------- Point norms: qn2/kn2 = sum over 48 point dims ----------------
__global__ void k_norms() {
    int t = threadIdx.x;
    int r = blockIdx.x * 8 + (t >> 5);   // row in [0, NBH*NS)
    int lane = t & 31;
    const float* q = g_Qc + (size_t)r * NCD + 64;
    const float* k = g_Kc + (size_t)r * NCD + 64;
    float qa = q[lane], ka = k[lane];
    float qb = 0.f, kb = 0.f;
    if (lane < 16) { qb = q[32 + lane]; kb = k[32 + lane]; }
    float qs = qa * qa + qb * qb;
    float ks = ka * ka + kb * kb;
#pragma unroll
    for (int o = 16; o > 0; o >>= 1) {
        qs += __shfl_xor_sync(0xffffffffu, qs, o);
        ks += __shfl_xor_sync(0xffffffffu, ks, o);
    }
    if (lane == 0) { g_qn2[r] = qs; g_kn2[r] = ks; }
}

// ---------------- Distance-MLP bias plane (masked, incl. -0.5(qn2+kn2)) ----------------
__global__ void k_bias(const float* __restrict__ coords,
                       const float* __restrict__ Wd1, const float* __restrict__ bd1,
                       const float* __restrict__ Wd2, const float* __restrict__ bd2) {
    int q = blockIdx.x, b = blockIdx.y, tid = threadIdx.x;
    __shared__ float w1[32], c1[32], w2[256], c2[8];
    if (tid < 32) { w1[tid] = Wd1[tid]; c1[tid] = bd1[tid]; }
    if (tid < 8)  c2[tid] = bd2[tid];
    w2[tid] = Wd2[tid];
    __syncthreads();
    float cqx = coords[((size_t)b * NS + q) * 3 + 0];
    float cqy = coords[((size_t)b * NS + q) * 3 + 1];
    float cqz = coords[((size_t)b * NS + q) * 3 + 2];
    float qn2v[8];
#pragma unroll
    for (int h = 0; h < 8; h++) qn2v[h] = g_qn2[(b * 8 + h) * NS + q];
    for (int k = tid; k < NS; k += 256) {
        float dx = cqx - coords[((size_t)b * NS + k) * 3 + 0];
        float dy = cqy - coords[((size_t)b * NS + k) * 3 + 1];
        float dz = cqz - coords[((size_t)b * NS + k) * 3 + 2];
        float dist = sqrtf(dx * dx + dy * dy + dz * dz);
        if (dist < 15.0f) {
            float hb[8];
#pragma unroll
            for (int h = 0; h < 8; h++) hb[h] = c2[h];
#pragma unroll
            for (int jj = 0; jj < 32; jj++) {
                float hv = fmaxf(fmaf(dist, w1[jj], c1[jj]), 0.0f);
#pragma unroll
                for (int h = 0; h < 8; h++) hb[h] = fmaf(hv, w2[jj * 8 + h], hb[h]);
            }
#pragma unroll
            for (int h = 0; h < 8; h++) {
                int bh = b * 8 + h;
                g_bias[((size_t)bh * NS + q) * NS + k] =
                    hb[h] - 0.5f * (qn2v[h] + g_kn2[bh * NS + k]);
            }
        } else {
#pragma unroll
            for (int h = 0; h < 8; h++) {
                int bh = b * 8 + h;
                g_bias[((size_t)bh * NS + q) * NS + k] = -1e30f;
            }
        }
    }
}

// ---------------- Softmax over k (in place on g_T), float4 ----------------
__global__ void k_softmax() {
    float4* p = (float4*)(g_T + (size_t)blockIdx.x * NS);
    int tid = threadIdx.x;
    float4 v = p[tid];
    float m = fmaxf(fmaxf(v.x, v.y), fmaxf(v.z, v.w));
    __shared__ float red[256];
    red[tid] = m; __syncthreads();
    for (int s = 128; s > 0; s >>= 1) { if (tid < s) red[tid] = fmaxf(red[tid], red[tid + s]); __syncthreads(); }
    m = red[0];
    __syncthreads();
    v.x = __expf(v.x - m); v.y = __expf(v.y - m);
    v.z = __expf(v.z - m); v.w = __expf(v.w - m);
    float sum = v.x + v.y + v.z + v.w;
    red[tid] = sum; __syncthreads();
    for (int s = 128; s > 0; s >>= 1) { if (tid < s) red[tid] += red[tid + s]; __syncthreads(); }
    float inv = 1.0f / red[0];
    v.x *= inv; v.y *= inv; v.z *= inv; v.w *= inv;
    p[tid] = v;
}

// ---------------- Coords update ----------------
__global__ void k_coords(const float* __restrict__ coords, float* __restrict__ outc) {
    int idx = blockIdx.x * 256 + threadIdx.x;
    if (idx >= NROWS * 3) return;
    int row = idx / 3, c = idx % 3;
    const float* ap = g_att + (size_t)row * ATT_W + 512;
    float s = 0.f;
#pragma unroll 8
    for (int t = 0; t < 128; t++) s += ap[t * 3 + c];
    outc[idx] = coords[idx] + 0.1f * s * (1.0f / 128.0f);
}

// ---------------- Launch ----------------
extern "C" void kernel_launch(void* const* d_in, const int* in_sizes, int n_in,
                              void* d_out, int out_size) {
    const float* x      = (const float*)d_in[0];
    const float* coords = (const float*)d_in[1];
    const float* Wq     = (const float*)d_in[2];
    const float* Wk     = (const float*)d_in[3];
    const float* Wv     = (const float*)d_in[4];
    const float* Wqp    = (const float*)d_in[5];
    const float* bqp    = (const float*)d_in[6];
    const float* Wkp    = (const float*)d_in[7];
    const float* bkp    = (const float*)d_in[8];
    const float* Wvp    = (const float*)d_in[9];
    const float* bvp    = (const float*)d_in[10];
    const float* Wd1    = (const float*)d_in[11];
    const float* bd1    = (const float*)d_in[12];
    const float* Wd2    = (const float*)d_in[13];
    const float* bd2    = (const float*)d_in[14];
    const float* Wo     = (const float*)d_in[15];
    const float* bo     = (const float*)d_in[16];
    const float* g1     = (const float*)d_in[17];
    const float* b1     = (const float*)d_in[18];
    const float* g2     = (const float*)d_in[19];
    const float* b2     = (const float*)d_in[20];
    float* out = (float*)d_out;

    float *p_xn, *p_wcat, *p_proj, *p_att, *p_pre;
    cudaGetSymbolAddress((void**)&p_xn,   g_xn);
    cudaGetSymbolAddress((void**)&p_wcat, g_Wcat);
    cudaGetSymbolAddress((void**)&p_proj, g_proj);
    cudaGetSymbolAddress((void**)&p_att,  g_att);
    cudaGetSymbolAddress((void**)&p_pre,  g_pre);

    // 1. LayerNorm
    k_ln<<<NROWS, 256>>>(x, nullptr, g1, b1, p_xn);
    // 2. Concatenated projection weights + fused projection GEMM (2048x2688x512)
    k_wcat<<<(ND * NCAT + 255) / 256, 256>>>(Wq, Wk, Wv, Wqp, Wkp, Wvp);
    gemm_nn<8><<<dim3(NCAT / 128, NROWS / 128), 256>>>(NROWS, NCAT, ND, p_xn, p_wcat, nullptr, p_proj);
    // 3. Rearrange into per-(b,h) concat Q/K/V (row-major, coalesced)
    k_rearrange<<<NROWS, 128>>>(coords, bqp, bkp, bvp);
    // 4. Point norms
    k_norms<<<NBH * NS / 8, 256>>>();
    // 5. Distance-MLP bias plane with mask + norm terms
    k_bias<<<dim3(NS, NB), 256>>>(coords, Wd1, bd1, Wd2, bd2);
    // 6. Logits GEMM (NT, attn + point dot fused, K=112)
    k_logits<<<dim3(NS / 128, NS / 128, NBH), 256>>>();
    // 7. Softmax
    k_softmax<<<NBH * NS, 256>>>();
    // 8. AV GEMM (feature + point values fused, N=112)
    k_av<<<dim3(1, NS / 128, NBH), 256>>>();
    // 9. Output projection (2048x512x896)
    gemm_nn<4><<<dim3(ND / 128, NROWS / 64), 256>>>(NROWS, ND, ATT_W, p_att, Wo, bo, p_pre);
    // 10. Residual + final LayerNorm -> out
    k_ln<<<NROWS, 256>>>(x, p_pre, g2, b2, out);
    // 11. Coords update -> second output
    k_coords<<<(NROWS * 3 + 255) / 256, 256>>>(coords, out + (size_t)NROWS * ND);
}

// round 3
// speedup vs baseline: 1.3378x; 1.0933x over previous
#include <cuda_runtime.h>
#include <math.h>

// Problem constants
#define NB 2
#define NS 1024
#define ND 512
#define NH 8
#define NCAT 2688           // 3*512 + 3*384
#define NCD 112             // 64 + 48
#define NBH 16              // NB*NH
#define NROWS 2048          // NB*NS
#define ATT_W 896           // ND + NHP3

// Fused attention tiling
#define FBM 128
#define FBK 64
#define QS_LD 130
#define KS_LD 66
#define VS_LD 116
#define PS_LD 130

// Scratch (static device memory; no runtime allocation)
__device__ float g_xn[NROWS * ND];
__device__ float g_Wcat[ND * NCAT];
__device__ float g_proj[NROWS * NCAT];
__device__ float g_Qc[NBH * NS * NCD];
__device__ float g_Kc[NBH * NS * NCD];
__device__ float g_Vc[NBH * NS * NCD];
__device__ float g_qn2[NBH * NS];
__device__ float g_kn2[NBH * NS];
__device__ float g_att[NROWS * ATT_W];
__device__ float g_pre[NROWS * ND];

// ---------------- f32x2 packed helpers ----------------
__device__ __forceinline__ unsigned long long dup2(float x) {
    unsigned long long r; unsigned u = __float_as_uint(x);
    asm("mov.b64 %0, {%1, %1};" : "=l"(r) : "r"(u));
    return r;
}
__device__ __forceinline__ unsigned long long pack2(float lo, float hi) {
    unsigned long long r;
    asm("mov.b64 %0, {%1, %2};" : "=l"(r) : "r"(__float_as_uint(lo)), "r"(__float_as_uint(hi)));
    return r;
}
__device__ __forceinline__ void ffma2(unsigned long long& c, unsigned long long a, unsigned long long b) {
    asm("fma.rn.f32x2 %0, %1, %2, %0;" : "+l"(c) : "l"(a), "l"(b));
}
__device__ __forceinline__ void mul2(unsigned long long& c, unsigned long long a) {
    asm("mul.rn.f32x2 %0, %0, %1;" : "+l"(c) : "l"(a));
}
__device__ __forceinline__ void unpk(unsigned long long v, float& lo, float& hi) {
    unsigned a, b;
    asm("mov.b64 {%0, %1}, %2;" : "=r"(a), "=r"(b) : "l"(v));
    lo = __uint_as_float(a); hi = __uint_as_float(b);
}

// ---------------- LayerNorm (optionally with residual add) ----------------
__global__ void k_ln(const float* __restrict__ x, const float* __restrict__ res,
                     const float* __restrict__ g, const float* __restrict__ b,
                     float* __restrict__ y) {
    int row = blockIdx.x, tid = threadIdx.x;
    const float* xr = x + (size_t)row * ND;
    float v0 = xr[tid], v1 = xr[tid + 256];
    if (res) {
        v0 += res[(size_t)row * ND + tid];
        v1 += res[(size_t)row * ND + tid + 256];
    }
    __shared__ float red[256];
    red[tid] = v0 + v1;
    __syncthreads();
    for (int s = 128; s > 0; s >>= 1) { if (tid < s) red[tid] += red[tid + s]; __syncthreads(); }
    float mean = red[0] * (1.0f / ND);
    __syncthreads();
    float d0 = v0 - mean, d1 = v1 - mean;
    red[tid] = d0 * d0 + d1 * d1;
    __syncthreads();
    for (int s = 128; s > 0; s >>= 1) { if (tid < s) red[tid] += red[tid + s]; __syncthreads(); }
    float rstd = rsqrtf(red[0] * (1.0f / ND) + 1e-5f);
    float* yr = y + (size_t)row * ND;
    yr[tid]       = d0 * rstd * g[tid] + b[tid];
    yr[tid + 256] = d1 * rstd * g[tid + 256] + b[tid + 256];
}

// ---------------- Concatenate projection weights into [512 x 2688] ----------------
__global__ void k_wcat(const float* __restrict__ Wq, const float* __restrict__ Wk,
                       const float* __restrict__ Wv, const float* __restrict__ Wqp,
                       const float* __restrict__ Wkp, const float* __restrict__ Wvp) {
    int idx = blockIdx.x * 256 + threadIdx.x;
    if (idx >= ND * NCAT) return;
    int k = idx / NCAT, c = idx % NCAT;
    float v;
    if      (c < 512)  v = Wq[k * 512 + c];
    else if (c < 1024) v = Wk[k * 512 + (c - 512)];
    else if (c < 1536) v = Wv[k * 512 + (c - 1024)];
    else if (c < 1920) v = Wqp[k * 384 + (c - 1536)];
    else if (c < 2304) v = Wkp[k * 384 + (c - 1920)];
    else               v = Wvp[k * 384 + (c - 2304)];
    g_Wcat[idx] = v;
}

// ---------------- NN SGEMM: C = A[MxK] @ B[KxN] (+ bias). f32x2 FMA, double buffered ----
template<int TM>
__global__ void __launch_bounds__(256, 2)
gemm_nn(int M, int N, int K,
        const float* __restrict__ A, const float* __restrict__ B,
        const float* __restrict__ bias, float* __restrict__ C)
{
    constexpr int BM = TM * 16;
    constexpr int AP = BM + 4;
    constexpr int LA = BM / 64;
    __shared__ float As[2][16][AP];
    __shared__ float Bs[2][16][128];
    const int tid = threadIdx.x;
    const int tn = tid & 15, tm = tid >> 4;
    const int m0 = tm * TM, n0 = tn * 8;
    const int rb = blockIdx.y * BM, cb = blockIdx.x * 128;

    unsigned long long acc[TM][4];
#pragma unroll
    for (int i = 0; i < TM; i++)
#pragma unroll
        for (int j = 0; j < 4; j++) acc[i][j] = 0ull;

    int aR[LA], aC[LA];
#pragma unroll
    for (int i = 0; i < LA; i++) { int idx = tid + i * 256; aR[i] = idx >> 2; aC[i] = (idx & 3) * 4; }
    int bR[2], bC[2];
#pragma unroll
    for (int i = 0; i < 2; i++)  { int idx = tid + i * 256; bR[i] = idx >> 5; bC[i] = (idx & 31) * 4; }

    float4 av[LA], bv[2];
#pragma unroll
    for (int i = 0; i < LA; i++)
        av[i] = *(const float4*)(A + (size_t)(rb + aR[i]) * K + aC[i]);
#pragma unroll
    for (int i = 0; i < 2; i++) {
        int col = cb + bC[i];
        bv[i] = (col < N) ? *(const float4*)(B + (size_t)bR[i] * N + col)
                          : make_float4(0.f, 0.f, 0.f, 0.f);
    }
#pragma unroll
    for (int i = 0; i < LA; i++) {
        As[0][aC[i] + 0][aR[i]] = av[i].x;
        As[0][aC[i] + 1][aR[i]] = av[i].y;
        As[0][aC[i] + 2][aR[i]] = av[i].z;
        As[0][aC[i] + 3][aR[i]] = av[i].w;
    }
#pragma unroll
    for (int i = 0; i < 2; i++)
        *(float4*)&Bs[0][bR[i]][bC[i]] = bv[i];
    __syncthreads();

    int buf = 0;
    for (int k0 = 0; k0 < K; k0 += 16) {
        const bool nxt = (k0 + 16) < K;
        if (nxt) {
#pragma unroll
            for (int i = 0; i < LA; i++)
                av[i] = *(const float4*)(A + (size_t)(rb + aR[i]) * K + k0 + 16 + aC[i]);
#pragma unroll
            for (int i = 0; i < 2; i++) {
                int col = cb + bC[i];
                bv[i] = (col < N) ? *(const float4*)(B + (size_t)(k0 + 16 + bR[i]) * N + col)
                                  : make_float4(0.f, 0.f, 0.f, 0.f);
            }
        }
#pragma unroll
        for (int kk = 0; kk < 16; kk++) {
            unsigned long long bb[4], ad[TM];
#pragma unroll
            for (int j = 0; j < 4; j++)
                bb[j] = *(const unsigned long long*)&Bs[buf][kk][n0 + 2 * j];
#pragma unroll
            for (int i = 0; i < TM; i++)
                ad[i] = dup2(As[buf][kk][m0 + i]);
#pragma unroll
            for (int i = 0; i < TM; i++)
#pragma unroll
                for (int j = 0; j < 4; j++)
                    ffma2(acc[i][j], ad[i], bb[j]);
        }
        if (nxt) {
            int nb = buf ^ 1;
#pragma unroll
            for (int i = 0; i < LA; i++) {
                As[nb][aC[i] + 0][aR[i]] = av[i].x;
                As[nb][aC[i] + 1][aR[i]] = av[i].y;
                As[nb][aC[i] + 2][aR[i]] = av[i].z;
                As[nb][aC[i] + 3][aR[i]] = av[i].w;
            }
#pragma unroll
            for (int i = 0; i < 2; i++)
                *(float4*)&Bs[nb][bR[i]][bC[i]] = bv[i];
            __syncthreads();
            buf = nb;
        }
    }

#pragma unroll
    for (int i = 0; i < TM; i++) {
        int r = rb + m0 + i;
#pragma unroll
        for (int j = 0; j < 4; j++) {
            int c = cb + n0 + 2 * j;
            if (c >= N) continue;
            float lo, hi; unpk(acc[i][j], lo, hi);
            if (bias) { lo += bias[c]; hi += bias[c + 1]; }
            C[(size_t)r * N + c]     = lo;
            C[(size_t)r * N + c + 1] = hi;
        }
    }
}

// ---------------- Rearrange: build Qc/Kc/Vc rows (all coalesced) ----------------
__global__ void k_rearrange(const float* __restrict__ coords,
                            const float* __restrict__ bqp, const float* __restrict__ bkp,
                            const float* __restrict__ bvp) {
    int row = blockIdx.x;              // b*1024+s
    int b = row >> 10, s = row & 1023;
    int j = threadIdx.x;               // 0..127
    if (j >= NCD) return;
    const float* pr = g_proj + (size_t)row * NCAT;
    float ce = 0.f; int jj = 0;
    if (j >= 64) { jj = j - 64; ce = coords[(size_t)row * 3 + (jj % 3)]; }
#pragma unroll
    for (int h = 0; h < NH; h++) {
        size_t o = ((size_t)(b * NH + h) * NS + s) * NCD + j;
        if (j < 64) {
            g_Qc[o] = pr[h * 64 + j] * 0.125f;     // SCALE = 1/8
            g_Kc[o] = pr[512 + h * 64 + j];
            g_Vc[o] = pr[1024 + h * 64 + j];
        } else {
            g_Qc[o] = pr[1536 + h * 48 + jj] + bqp[h * 48 + jj] + ce;
            g_Kc[o] = pr[1920 + h * 48 + jj] + bkp[h * 48 + jj] + ce;
            g_Vc[o] = pr[2304 + h * 48 + jj] + bvp[h * 48 + jj];
        }
    }
}

// ---------------- Point norms ----------------
__global__ void k_norms() {
    int t = threadIdx.x;
    int r = blockIdx.x * 8 + (t >> 5);
    int lane = t & 31;
    const float* q = g_Qc + (size_t)r * NCD + 64;
    const float* k = g_Kc + (size_t)r * NCD + 64;
    float qa = q[lane], ka = k[lane];
    float qb = 0.f, kb = 0.f;
    if (lane < 16) { qb = q[32 + lane]; kb = k[32 + lane]; }
    float qs = qa * qa + qb * qb;
    float ks = ka * ka + kb * kb;
#pragma unroll
    for (int o = 16; o > 0; o >>= 1) {
        qs += __shfl_xor_sync(0xffffffffu, qs, o);
        ks += __shfl_xor_sync(0xffffffffu, ks, o);
    }
    if (lane == 0) { g_qn2[r] = qs; g_kn2[r] = ks; }
}

// ---------------- Fused attention: S=QK^T + bias + mask -> online softmax -> O=PV -------
// One block per (bh, 128-row q strip). 256 threads, 16x16, 8 rows x (4 S-cols / 7 O-cols).
__global__ void __launch_bounds__(256, 1)
k_attn(const float* __restrict__ coords,
       const float* __restrict__ Wd1, const float* __restrict__ bd1,
       const float* __restrict__ Wd2, const float* __restrict__ bd2)
{
    extern __shared__ float smp[];
    float* Qs   = smp;                    // [112][130] transposed
    float* Ks   = Qs + 112 * QS_LD;       // [112][66]  transposed
    float* Vs   = Ks + 112 * KS_LD;       // [64][116]  natural
    float* Ps   = Vs + 64 * VS_LD;        // [64][130]  transposed (key-major)
    float* cqx  = Ps + 64 * PS_LD;
    float* cqy  = cqx + FBM;
    float* cqz  = cqy + FBM;
    float* qn2s = cqz + FBM;              // [128]
    float* ckx  = qn2s + FBM;
    float* cky  = ckx + FBK;
    float* ckz  = cky + FBK;
    float* kn2s = ckz + FBK;              // [64]
    float* kn   = kn2s + FBK;             // [64] knot table
    float* al   = kn + 64;                // [33]
    float* be   = al + 33;                // [33]

    const int bh = blockIdx.y;
    const int b  = bh >> 3, h = bh & 7;
    const int rb = blockIdx.x * FBM;
    const int tid = threadIdx.x;
    const int tm = tid >> 4, tn = tid & 15;
    const int m0 = tm * 8, n0s = tn * 4, n0o = tn * 7;

    const float* Qg = g_Qc + (size_t)bh * NS * NCD;
    const float* Kg = g_Kc + (size_t)bh * NS * NCD;
    const float* Vg = g_Vc + (size_t)bh * NS * NCD;

    // ---- Build exact piecewise-linear LUT for hbias_h(d) on (0,15): thread 0 ----
    if (tid == 0) {
        float kj[32], da_[32], db_[32];
        int m = 0;
        float a0 = 0.f, b0 = bd2[h];
        for (int j = 0; j < 32; j++) {
            float w = Wd1[j], c = bd1[j], u = Wd2[j * 8 + h];
            if (w > 0.f) {
                float kk = -c / w;
                if (kk <= 0.f) { a0 += w * u; b0 += c * u; }                 // always active
                else if (kk < 15.f) { kj[m] = kk; da_[m] = w * u; db_[m] = c * u; m++; }
            } else if (w < 0.f) {
                float kk = -c / w;
                if (kk >= 15.f) { a0 += w * u; b0 += c * u; }                // always active
                else if (kk > 0.f) {
                    a0 += w * u; b0 += c * u;                                // active at d->0+
                    kj[m] = kk; da_[m] = -w * u; db_[m] = -c * u; m++;       // deactivates at kk
                }
            } else if (c > 0.f) { b0 += c * u; }
        }
        for (int i = 1; i < m; i++) {     // insertion sort
            float kv = kj[i], av = da_[i], bv = db_[i]; int p = i - 1;
            while (p >= 0 && kj[p] > kv) {
                kj[p + 1] = kj[p]; da_[p + 1] = da_[p]; db_[p + 1] = db_[p]; p--;
            }
            kj[p + 1] = kv; da_[p + 1] = av; db_[p + 1] = bv;
        }
        kn[0] = -1e30f; al[0] = a0; be[0] = b0;
        for (int i = 0; i < m; i++) {
            kn[i + 1] = kj[i];
            al[i + 1] = al[i] + da_[i];
            be[i + 1] = be[i] + db_[i];
        }
        for (int i = m + 1; i < 64; i++) kn[i] = 1e30f;
    }

    // ---- Load Q strip (transposed) + per-row data ----
#pragma unroll
    for (int t = 0; t < 14; t++) {
        int idx = tid + t * 256;
        int m = idx / 28, c4 = (idx % 28) * 4;
        float4 v = *(const float4*)(Qg + (size_t)(rb + m) * NCD + c4);
        Qs[(c4 + 0) * QS_LD + m] = v.x;
        Qs[(c4 + 1) * QS_LD + m] = v.y;
        Qs[(c4 + 2) * QS_LD + m] = v.z;
        Qs[(c4 + 3) * QS_LD + m] = v.w;
    }
    if (tid < FBM) {
        int q = rb + tid;
        cqx[tid] = coords[((size_t)b * NS + q) * 3 + 0];
        cqy[tid] = coords[((size_t)b * NS + q) * 3 + 1];
        cqz[tid] = coords[((size_t)b * NS + q) * 3 + 2];
        qn2s[tid] = g_qn2[bh * NS + q];
    }

    unsigned long long accO[4][7];
#pragma unroll
    for (int t = 0; t < 4; t++)
#pragma unroll
        for (int c = 0; c < 7; c++) accO[t][c] = 0ull;
    float run_m[8], run_s[8];
#pragma unroll
    for (int i = 0; i < 8; i++) { run_m[i] = -1e30f; run_s[i] = 0.f; }

    for (int kb = 0; kb < NS; kb += FBK) {
        __syncthreads();   // Ks/Vs free (prev PV done); first iter: Q/LUT ready

        // load K (transposed), V (natural), k-side coords/norms
#pragma unroll
        for (int t = 0; t < 7; t++) {
            int idx = tid + t * 256;
            int key = idx / 28, c4 = (idx % 28) * 4;
            float4 kv = *(const float4*)(Kg + (size_t)(kb + key) * NCD + c4);
            Ks[(c4 + 0) * KS_LD + key] = kv.x;
            Ks[(c4 + 1) * KS_LD + key] = kv.y;
            Ks[(c4 + 2) * KS_LD + key] = kv.z;
            Ks[(c4 + 3) * KS_LD + key] = kv.w;
            float4 vv = *(const float4*)(Vg + (size_t)(kb + key) * NCD + c4);
            *(float4*)(Vs + key * VS_LD + c4) = vv;
        }
        if (tid < FBK) {
            int kk = kb + tid;
            ckx[tid] = coords[((size_t)b * NS + kk) * 3 + 0];
            cky[tid] = coords[((size_t)b * NS + kk) * 3 + 1];
            ckz[tid] = coords[((size_t)b * NS + kk) * 3 + 2];
            kn2s[tid] = g_kn2[bh * NS + kk];
        }
        __syncthreads();

        // ---- S = Q * K^T tile (128x64), f32x2 pairs along m ----
        unsigned long long accS[4][4];
#pragma unroll
        for (int t = 0; t < 4; t++)
#pragma unroll
            for (int j = 0; j < 4; j++) accS[t][j] = 0ull;
#pragma unroll 4
        for (int d = 0; d < NCD; d++) {
            const float* qr = Qs + d * QS_LD + m0;
            const float* kr = Ks + d * KS_LD + n0s;
            unsigned long long ap[4], bd[4];
#pragma unroll
            for (int t = 0; t < 4; t++) ap[t] = *(const unsigned long long*)(qr + 2 * t);
#pragma unroll
            for (int j = 0; j < 4; j++) bd[j] = dup2(kr[j]);
#pragma unroll
            for (int t = 0; t < 4; t++)
#pragma unroll
                for (int j = 0; j < 4; j++) ffma2(accS[t][j], ap[t], bd[j]);
        }
        float Sv[8][4];
#pragma unroll
        for (int t = 0; t < 4; t++)
#pragma unroll
            for (int j = 0; j < 4; j++) unpk(accS[t][j], Sv[2 * t][j], Sv[2 * t + 1][j]);

        // ---- bias + mask epilogue ----
#pragma unroll
        for (int i = 0; i < 8; i++) {
            float qx = cqx[m0 + i], qy = cqy[m0 + i], qz = cqz[m0 + i];
            float qn = qn2s[m0 + i];
#pragma unroll
            for (int j = 0; j < 4; j++) {
                int gk = n0s + j;
                float dx = qx - ckx[gk], dy = qy - cky[gk], dz = qz - ckz[gk];
                float d2 = fmaf(dx, dx, fmaf(dy, dy, dz * dz));
                if (d2 < 225.f) {
                    float d = sqrtf(d2);
                    int idx = 0;
#pragma unroll
                    for (int st = 32; st > 0; st >>= 1)
                        if (kn[idx + st] <= d) idx += st;
                    Sv[i][j] += fmaf(al[idx], d, be[idx]) - 0.5f * (qn + kn2s[gk]);
                } else {
                    Sv[i][j] = -1e9f;
                }
            }
        }

        // ---- online softmax (rows shared by 16 consecutive lanes) ----
        float scl[8];
#pragma unroll
        for (int i = 0; i < 8; i++) {
            float mx = fmaxf(fmaxf(Sv[i][0], Sv[i][1]), fmaxf(Sv[i][2], Sv[i][3]));
#pragma unroll
            for (int o = 8; o > 0; o >>= 1) mx = fmaxf(mx, __shfl_xor_sync(0xffffffffu, mx, o));
            float nm = fmaxf(run_m[i], mx);
            float sc = __expf(run_m[i] - nm);
            float ts = 0.f;
#pragma unroll
            for (int j = 0; j < 4; j++) { float p = __expf(Sv[i][j] - nm); Sv[i][j] = p; ts += p; }
#pragma unroll
            for (int o = 8; o > 0; o >>= 1) ts += __shfl_xor_sync(0xffffffffu, ts, o);
            run_s[i] = run_s[i] * sc + ts;
            run_m[i] = nm;
            scl[i] = sc;
        }
#pragma unroll
        for (int t = 0; t < 4; t++) {
            unsigned long long sp = pack2(scl[2 * t], scl[2 * t + 1]);
#pragma unroll
            for (int c = 0; c < 7; c++) mul2(accO[t][c], sp);
        }

        // ---- write P (key-major) ----
#pragma unroll
        for (int i = 0; i < 8; i++)
#pragma unroll
            for (int j = 0; j < 4; j++)
                Ps[(n0s + j) * PS_LD + (m0 + i)] = Sv[i][j];
        __syncthreads();

        // ---- O += P * V ----
#pragma unroll 2
        for (int kk = 0; kk < FBK; kk++) {
            const float* pr = Ps + kk * PS_LD + m0;
            const float* vr = Vs + kk * VS_LD + n0o;
            unsigned long long ap[4];
#pragma unroll
            for (int t = 0; t < 4; t++) ap[t] = *(const unsigned long long*)(pr + 2 * t);
#pragma unroll
            for (int c = 0; c < 7; c++) {
                unsigned long long bd = dup2(vr[c]);
#pragma unroll
                for (int t = 0; t < 4; t++) ffma2(accO[t][c], ap[t], bd);
            }
        }
    }

    // ---- finalize: normalize + scatter into concat layout ----
    float inv[8];
#pragma unroll
    for (int i = 0; i < 8; i++) inv[i] = 1.0f / run_s[i];
#pragma unroll
    for (int t = 0; t < 4; t++) {
        int q0 = rb + m0 + 2 * t;
        size_t base0 = (size_t)(b * NS + q0) * ATT_W;
        size_t base1 = base0 + ATT_W;
#pragma unroll
        for (int c = 0; c < 7; c++) {
            int col = n0o + c;
            int cc = (col < 64) ? (h * 64 + col) : (512 + h * 48 + (col - 64));
            float o0, o1; unpk(accO[t][c], o0, o1);
            g_att[base0 + cc] = o0 * inv[2 * t];
            g_att[base1 + cc] = o1 * inv[2 * t + 1];
        }
    }
}

// ---------------- Coords update (block per row) ----------------
__global__ void k_coords(const float* __restrict__ coords, float* __restrict__ outc) {
    int row = blockIdx.x, t = threadIdx.x;   // 128 threads
    const float* ap = g_att + (size_t)row * ATT_W + 512;
    __shared__ float sx[128], sy[128], sz[128];
    sx[t] = ap[t * 3 + 0]; sy[t] = ap[t * 3 + 1]; sz[t] = ap[t * 3 + 2];
    __syncthreads();
    for (int s = 64; s > 0; s >>= 1) {
        if (t < s) { sx[t] += sx[t + s]; sy[t] += sy[t + s]; sz[t] += sz[t + s]; }
        __syncthreads();
    }
    if (t == 0) {
        outc[row * 3 + 0] = coords[row * 3 + 0] + sx[0] * (0.1f / 128.f);
        outc[row * 3 + 1] = coords[row * 3 + 1] + sy[0] * (0.1f / 128.f);
        outc[row * 3 + 2] = coords[row * 3 + 2] + sz[0] * (0.1f / 128.f);
    }
}

// ---------------- Launch ----------------
extern "C" void kernel_launch(void* const* d_in, const int* in_sizes, int n_in,
                              void* d_out, int out_size) {
    const float* x      = (const float*)d_in[0];
    const float* coords = (const float*)d_in[1];
    const float* Wq     = (const float*)d_in[2];
    const float* Wk     = (const float*)d_in[3];
    const float* Wv     = (const float*)d_in[4];
    const float* Wqp    = (const float*)d_in[5];
    const float* bqp    = (const float*)d_in[6];
    const float* Wkp    = (const float*)d_in[7];
    const float* bkp    = (const float*)d_in[8];
    const float* Wvp    = (const float*)d_in[9];
    const float* bvp    = (const float*)d_in[10];
    const float* Wd1    = (const float*)d_in[11];
    const float* bd1    = (const float*)d_in[12];
    const float* Wd2    = (const float*)d_in[13];
    const float* bd2    = (const float*)d_in[14];
    const float* Wo     = (const float*)d_in[15];
    const float* bo     = (const float*)d_in[16];
    const float* g1     = (const float*)d_in[17];
    const float* b1     = (const float*)d_in[18];
    const float* g2     = (const float*)d_in[19];
    const float* b2     = (const float*)d_in[20];
    float* out = (float*)d_out;

    float *p_xn, *p_wcat, *p_proj, *p_att, *p_pre;
    cudaGetSymbolAddress((void**)&p_xn,   g_xn);
    cudaGetSymbolAddress((void**)&p_wcat, g_Wcat);
    cudaGetSymbolAddress((void**)&p_proj, g_proj);
    cudaGetSymbolAddress((void**)&p_att,  g_att);
    cudaGetSymbolAddress((void**)&p_pre,  g_pre);

    // Fused-attention dynamic smem size
    const int smem_attn = (112 * QS_LD + 112 * KS_LD + 64 * VS_LD + 64 * PS_LD +
                           4 * FBM + 4 * FBK + 64 + 33 + 33) * sizeof(float);
    static int attr_set = 0;
    cudaFuncSetAttribute(k_attn, cudaFuncAttributeMaxDynamicSharedMemorySize, smem_attn);
    (void)attr_set;

    // 1. LayerNorm
    k_ln<<<NROWS, 256>>>(x, nullptr, g1, b1, p_xn);
    // 2. Concatenated projection weights + fused projection GEMM (2048x2688x512)
    k_wcat<<<(ND * NCAT + 255) / 256, 256>>>(Wq, Wk, Wv, Wqp, Wkp, Wvp);
    gemm_nn<8><<<dim3(NCAT / 128, NROWS / 128), 256>>>(NROWS, NCAT, ND, p_xn, p_wcat, nullptr, p_proj);
    // 3. Rearrange into per-(b,h) concat Q/K/V
    k_rearrange<<<NROWS, 128>>>(coords, bqp, bkp, bvp);
    // 4. Point norms
    k_norms<<<NBH * NS / 8, 256>>>();
    // 5. Fused attention (logits + bias + mask + softmax + AV)
    k_attn<<<dim3(NS / FBM, NBH), 256, smem_attn>>>(coords, Wd1, bd1, Wd2, bd2);
    // 6. Output projection (2048x512x896)
    gemm_nn<4><<<dim3(ND / 128, NROWS / 64), 256>>>(NROWS, ND, ATT_W, p_att, Wo, bo, p_pre);
    // 7. Residual + final LayerNorm -> out
    k_ln<<<NROWS, 256>>>(x, p_pre, g2, b2, out);
    // 8. Coords update -> second output
    k_coords<<<NROWS, 128>>>(coords, out + (size_t)NROWS * ND);
}

// round 4
// speedup vs baseline: 1.4406x; 1.0769x over previous
#include <cuda_runtime.h>
#include <math.h>

// Problem constants
#define NB 2
#define NS 1024
#define ND 512
#define NH 8
#define NCAT 2688           // 3*512 + 3*384
#define NCD 112             // 64 + 48
#define NBH 16              // NB*NH
#define NROWS 2048          // NB*NS
#define ATT_W 896           // ND + NHP3

// Fused attention tiling
#define FBM 128
#define FBK 64
#define QS_LD 132
#define KS_LD 68
#define VS_LD 116
#define PS_LD 130

// Scratch (static device memory; no runtime allocation)
__device__ float g_xn[NROWS * ND];
__device__ float g_Wcat[ND * NCAT];
__device__ float g_Qc[NBH * NS * NCD];
__device__ float g_Kc[NBH * NS * NCD];
__device__ float g_Vc[NBH * NS * NCD];
__device__ float g_qn2[NBH * NS];
__device__ float g_kn2[NBH * NS];
__device__ float g_att[NROWS * ATT_W];
__device__ float g_pre[NROWS * ND];

// ---------------- f32x2 packed helpers ----------------
__device__ __forceinline__ unsigned long long dup2(float x) {
    unsigned long long r; unsigned u = __float_as_uint(x);
    asm("mov.b64 %0, {%1, %1};" : "=l"(r) : "r"(u));
    return r;
}
__device__ __forceinline__ unsigned long long pack2(float lo, float hi) {
    unsigned long long r;
    asm("mov.b64 %0, {%1, %2};" : "=l"(r) : "r"(__float_as_uint(lo)), "r"(__float_as_uint(hi)));
    return r;
}
__device__ __forceinline__ void ffma2(unsigned long long& c, unsigned long long a, unsigned long long b) {
    asm("fma.rn.f32x2 %0, %1, %2, %0;" : "+l"(c) : "l"(a), "l"(b));
}
__device__ __forceinline__ void mul2(unsigned long long& c, unsigned long long a) {
    asm("mul.rn.f32x2 %0, %0, %1;" : "+l"(c) : "l"(a));
}
__device__ __forceinline__ void unpk(unsigned long long v, float& lo, float& hi) {
    unsigned a, b;
    asm("mov.b64 {%0, %1}, %2;" : "=r"(a), "=r"(b) : "l"(v));
    lo = __uint_as_float(a); hi = __uint_as_float(b);
}

// ---------------- LayerNorm (optionally with residual add) ----------------
__global__ void k_ln(const float* __restrict__ x, const float* __restrict__ res,
                     const float* __restrict__ g, const float* __restrict__ b,
                     float* __restrict__ y) {
    int row = blockIdx.x, tid = threadIdx.x;
    const float* xr = x + (size_t)row * ND;
    float v0 = xr[tid], v1 = xr[tid + 256];
    if (res) {
        v0 += res[(size_t)row * ND + tid];
        v1 += res[(size_t)row * ND + tid + 256];
    }
    __shared__ float red[256];
    red[tid] = v0 + v1;
    __syncthreads();
    for (int s = 128; s > 0; s >>= 1) { if (tid < s) red[tid] += red[tid + s]; __syncthreads(); }
    float mean = red[0] * (1.0f / ND);
    __syncthreads();
    float d0 = v0 - mean, d1 = v1 - mean;
    red[tid] = d0 * d0 + d1 * d1;
    __syncthreads();
    for (int s = 128; s > 0; s >>= 1) { if (tid < s) red[tid] += red[tid + s]; __syncthreads(); }
    float rstd = rsqrtf(red[0] * (1.0f / ND) + 1e-5f);
    float* yr = y + (size_t)row * ND;
    yr[tid]       = d0 * rstd * g[tid] + b[tid];
    yr[tid + 256] = d1 * rstd * g[tid + 256] + b[tid + 256];
}

// ---------------- Concatenate projection weights into [512 x 2688] ----------------
__global__ void k_wcat(const float* __restrict__ Wq, const float* __restrict__ Wk,
                       const float* __restrict__ Wv, const float* __restrict__ Wqp,
                       const float* __restrict__ Wkp, const float* __restrict__ Wvp) {
    int idx = blockIdx.x * 256 + threadIdx.x;
    if (idx >= ND * NCAT) return;
    int k = idx / NCAT, c = idx % NCAT;
    float v;
    if      (c < 512)  v = Wq[k * 512 + c];
    else if (c < 1024) v = Wk[k * 512 + (c - 512)];
    else if (c < 1536) v = Wv[k * 512 + (c - 1024)];
    else if (c < 1920) v = Wqp[k * 384 + (c - 1536)];
    else if (c < 2304) v = Wkp[k * 384 + (c - 1920)];
    else               v = Wvp[k * 384 + (c - 2304)];
    g_Wcat[idx] = v;
}

// ---------------- Scatter element of projection into Qc/Kc/Vc ----------------
__device__ __forceinline__ void scatter_proj(
    int b, int s, int r, int c, float v, const float* __restrict__ coords,
    const float* __restrict__ bqp, const float* __restrict__ bkp, const float* __restrict__ bvp)
{
    if (c < 1536) {
        int seg = c >> 9;
        int cc = c & 511;
        int h = cc >> 6, j = cc & 63;
        size_t o = ((size_t)(b * NH + h) * NS + s) * NCD + j;
        if      (seg == 0) g_Qc[o] = v * 0.125f;   // SCALE = 1/8
        else if (seg == 1) g_Kc[o] = v;
        else               g_Vc[o] = v;
    } else {
        int t = c - 1536;
        int seg = t / 384;
        int cc = t - seg * 384;
        int h = cc / 48, jj = cc - h * 48;
        size_t o = ((size_t)(b * NH + h) * NS + s) * NCD + 64 + jj;
        if      (seg == 0) g_Qc[o] = v + bqp[cc] + coords[r * 3 + jj % 3];
        else if (seg == 1) g_Kc[o] = v + bkp[cc] + coords[r * 3 + jj % 3];
        else               g_Vc[o] = v + bvp[cc];
    }
}

// ---------------- Projection GEMM with scatter epilogue: g_xn @ g_Wcat -> Qc/Kc/Vc ------
// M=2048, N=2688, K=512. BM=BN=128, BK=16, 256 threads, 8x8/thread, f32x2, double buffered.
__global__ void __launch_bounds__(256, 2)
k_proj(const float* __restrict__ coords,
       const float* __restrict__ bqp, const float* __restrict__ bkp,
       const float* __restrict__ bvp)
{
    const float* A = g_xn;
    const float* B = g_Wcat;
    __shared__ float As[2][16][132];
    __shared__ float Bs[2][16][128];
    const int tid = threadIdx.x;
    const int tn = tid & 15, tm = tid >> 4;
    const int m0 = tm * 8, n0 = tn * 8;
    const int rb = blockIdx.y * 128, cb = blockIdx.x * 128;

    unsigned long long acc[8][4];
#pragma unroll
    for (int i = 0; i < 8; i++)
#pragma unroll
        for (int j = 0; j < 4; j++) acc[i][j] = 0ull;

    const int aR = tid >> 2, aC = (tid & 3) * 4;       // +i*64 rows
    const int bR = tid >> 5, bC = (tid & 31) * 4;      // +i*8 rows

    float4 av[2], bv[2];
#pragma unroll
    for (int i = 0; i < 2; i++) {
        av[i] = *(const float4*)(A + (size_t)(rb + aR + i * 64) * ND + aC);
        bv[i] = *(const float4*)(B + (size_t)(bR + i * 8) * NCAT + cb + bC);
    }
#pragma unroll
    for (int i = 0; i < 2; i++) {
        As[0][aC + 0][aR + i * 64] = av[i].x; As[0][aC + 1][aR + i * 64] = av[i].y;
        As[0][aC + 2][aR + i * 64] = av[i].z; As[0][aC + 3][aR + i * 64] = av[i].w;
        *(float4*)&Bs[0][bR + i * 8][bC] = bv[i];
    }
    __syncthreads();

    int buf = 0;
    for (int k0 = 0; k0 < ND; k0 += 16) {
        const bool nxt = (k0 + 16) < ND;
        if (nxt) {
#pragma unroll
            for (int i = 0; i < 2; i++) {
                av[i] = *(const float4*)(A + (size_t)(rb + aR + i * 64) * ND + k0 + 16 + aC);
                bv[i] = *(const float4*)(B + (size_t)(k0 + 16 + bR + i * 8) * NCAT + cb + bC);
            }
        }
#pragma unroll
        for (int kk = 0; kk < 16; kk++) {
            unsigned long long bb[4], ad[8];
#pragma unroll
            for (int j = 0; j < 4; j++)
                bb[j] = *(const unsigned long long*)&Bs[buf][kk][n0 + 2 * j];
#pragma unroll
            for (int i = 0; i < 8; i++)
                ad[i] = dup2(As[buf][kk][m0 + i]);
#pragma unroll
            for (int i = 0; i < 8; i++)
#pragma unroll
                for (int j = 0; j < 4; j++)
                    ffma2(acc[i][j], ad[i], bb[j]);
        }
        if (nxt) {
            int nb = buf ^ 1;
#pragma unroll
            for (int i = 0; i < 2; i++) {
                As[nb][aC + 0][aR + i * 64] = av[i].x; As[nb][aC + 1][aR + i * 64] = av[i].y;
                As[nb][aC + 2][aR + i * 64] = av[i].z; As[nb][aC + 3][aR + i * 64] = av[i].w;
                *(float4*)&Bs[nb][bR + i * 8][bC] = bv[i];
            }
            __syncthreads();
            buf = nb;
        }
    }

#pragma unroll
    for (int i = 0; i < 8; i++) {
        int r = rb + m0 + i;
        int b = r >> 10, s = r & 1023;
#pragma unroll
        for (int j = 0; j < 4; j++) {
            int c = cb + n0 + 2 * j;
            float lo, hi; unpk(acc[i][j], lo, hi);
            scatter_proj(b, s, r, c,     lo, coords, bqp, bkp, bvp);
            scatter_proj(b, s, r, c + 1, hi, coords, bqp, bkp, bvp);
        }
    }
}

// ---------------- NN SGEMM (output projection): C = A @ B + bias ----------------
template<int TM>
__global__ void __launch_bounds__(256, 2)
gemm_nn(int M, int N, int K,
        const float* __restrict__ A, const float* __restrict__ B,
        const float* __restrict__ bias, float* __restrict__ C)
{
    constexpr int BM = TM * 16;
    constexpr int AP = BM + 4;
    constexpr int LA = BM / 64;
    __shared__ float As[2][16][AP];
    __shared__ float Bs[2][16][128];
    const int tid = threadIdx.x;
    const int tn = tid & 15, tm = tid >> 4;
    const int m0 = tm * TM, n0 = tn * 8;
    const int rb = blockIdx.y * BM, cb = blockIdx.x * 128;

    unsigned long long acc[TM][4];
#pragma unroll
    for (int i = 0; i < TM; i++)
#pragma unroll
        for (int j = 0; j < 4; j++) acc[i][j] = 0ull;

    int aR[LA], aC[LA];
#pragma unroll
    for (int i = 0; i < LA; i++) { int idx = tid + i * 256; aR[i] = idx >> 2; aC[i] = (idx & 3) * 4; }
    int bR[2], bC[2];
#pragma unroll
    for (int i = 0; i < 2; i++)  { int idx = tid + i * 256; bR[i] = idx >> 5; bC[i] = (idx & 31) * 4; }

    float4 av[LA], bv[2];
#pragma unroll
    for (int i = 0; i < LA; i++)
        av[i] = *(const float4*)(A + (size_t)(rb + aR[i]) * K + aC[i]);
#pragma unroll
    for (int i = 0; i < 2; i++) {
        int col = cb + bC[i];
        bv[i] = (col < N) ? *(const float4*)(B + (size_t)bR[i] * N + col)
                          : make_float4(0.f, 0.f, 0.f, 0.f);
    }
#pragma unroll
    for (int i = 0; i < LA; i++) {
        As[0][aC[i] + 0][aR[i]] = av[i].x;
        As[0][aC[i] + 1][aR[i]] = av[i].y;
        As[0][aC[i] + 2][aR[i]] = av[i].z;
        As[0][aC[i] + 3][aR[i]] = av[i].w;
    }
#pragma unroll
    for (int i = 0; i < 2; i++)
        *(float4*)&Bs[0][bR[i]][bC[i]] = bv[i];
    __syncthreads();

    int buf = 0;
    for (int k0 = 0; k0 < K; k0 += 16) {
        const bool nxt = (k0 + 16) < K;
        if (nxt) {
#pragma unroll
            for (int i = 0; i < LA; i++)
                av[i] = *(const float4*)(A + (size_t)(rb + aR[i]) * K + k0 + 16 + aC[i]);
#pragma unroll
            for (int i = 0; i < 2; i++) {
                int col = cb + bC[i];
                bv[i] = (col < N) ? *(const float4*)(B + (size_t)(k0 + 16 + bR[i]) * N + col)
                                  : make_float4(0.f, 0.f, 0.f, 0.f);
            }
        }
#pragma unroll
        for (int kk = 0; kk < 16; kk++) {
            unsigned long long bb[4], ad[TM];
#pragma unroll
            for (int j = 0; j < 4; j++)
                bb[j] = *(const unsigned long long*)&Bs[buf][kk][n0 + 2 * j];
#pragma unroll
            for (int i = 0; i < TM; i++)
                ad[i] = dup2(As[buf][kk][m0 + i]);
#pragma unroll
            for (int i = 0; i < TM; i++)
#pragma unroll
                for (int j = 0; j < 4; j++)
                    ffma2(acc[i][j], ad[i], bb[j]);
        }
        if (nxt) {
            int nb = buf ^ 1;
#pragma unroll
            for (int i = 0; i < LA; i++) {
                As[nb][aC[i] + 0][aR[i]] = av[i].x;
                As[nb][aC[i] + 1][aR[i]] = av[i].y;
                As[nb][aC[i] + 2][aR[i]] = av[i].z;
                As[nb][aC[i] + 3][aR[i]] = av[i].w;
            }
#pragma unroll
            for (int i = 0; i < 2; i++)
                *(float4*)&Bs[nb][bR[i]][bC[i]] = bv[i];
            __syncthreads();
            buf = nb;
        }
    }

#pragma unroll
    for (int i = 0; i < TM; i++) {
        int r = rb + m0 + i;
#pragma unroll
        for (int j = 0; j < 4; j++) {
            int c = cb + n0 + 2 * j;
            if (c >= N) continue;
            float lo, hi; unpk(acc[i][j], lo, hi);
            if (bias) { lo += bias[c]; hi += bias[c + 1]; }
            C[(size_t)r * N + c]     = lo;
            C[(size_t)r * N + c + 1] = hi;
        }
    }
}

// ---------------- Point norms ----------------
__global__ void k_norms() {
    int t = threadIdx.x;
    int r = blockIdx.x * 8 + (t >> 5);
    int lane = t & 31;
    const float* q = g_Qc + (size_t)r * NCD + 64;
    const float* k = g_Kc + (size_t)r * NCD + 64;
    float qa = q[lane], ka = k[lane];
    float qb = 0.f, kb = 0.f;
    if (lane < 16) { qb = q[32 + lane]; kb = k[32 + lane]; }
    float qs = qa * qa + qb * qb;
    float ks = ka * ka + kb * kb;
#pragma unroll
    for (int o = 16; o > 0; o >>= 1) {
        qs += __shfl_xor_sync(0xffffffffu, qs, o);
        ks += __shfl_xor_sync(0xffffffffu, ks, o);
    }
    if (lane == 0) { g_qn2[r] = qs; g_kn2[r] = ks; }
}

// ---------------- Fused attention: S=QK^T + bias + mask -> online softmax -> O=PV -------
// 512 threads, 32x16 grid; per thread: 4 rows x (4 S-cols / 7 O-cols).
__global__ void __launch_bounds__(512, 1)
k_attn(const float* __restrict__ coords,
       const float* __restrict__ Wd1, const float* __restrict__ bd1,
       const float* __restrict__ Wd2, const float* __restrict__ bd2)
{
    extern __shared__ float smp[];
    float* Qs   = smp;                    // [112][132] transposed
    float* Ks   = Qs + 112 * QS_LD;       // [112][68]  transposed
    float* Vs   = Ks + 112 * KS_LD;       // [64][116]  natural
    float* Ps   = Vs + 64 * VS_LD;        // [64][130]  key-major
    float* cqx  = Ps + 64 * PS_LD;
    float* cqy  = cqx + FBM;
    float* cqz  = cqy + FBM;
    float* qn2s = cqz + FBM;
    float* ckx  = qn2s + FBM;
    float* cky  = ckx + FBK;
    float* ckz  = cky + FBK;
    float* kn2s = ckz + FBK;
    float* kn   = kn2s + FBK;             // [64] knot table
    float* al   = kn + 64;                // [33]
    float* be   = al + 33;                // [33]

    const int bh = blockIdx.y;
    const int b  = bh >> 3, h = bh & 7;
    const int rb = blockIdx.x * FBM;
    const int tid = threadIdx.x;
    const int tm = tid >> 4, tn = tid & 15;   // 32 x 16
    const int m0 = tm * 4, n0s = tn * 4, n0o = tn * 7;

    const float* Qg = g_Qc + (size_t)bh * NS * NCD;
    const float* Kg = g_Kc + (size_t)bh * NS * NCD;
    const float* Vg = g_Vc + (size_t)bh * NS * NCD;

    // ---- Exact piecewise-linear LUT for hbias_h(d) on (0,15) ----
    if (tid == 0) {
        float kj[32], da_[32], db_[32];
        int m = 0;
        float a0 = 0.f, b0 = bd2[h];
        for (int j = 0; j < 32; j++) {
            float w = Wd1[j], c = bd1[j], u = Wd2[j * 8 + h];
            if (w > 0.f) {
                float kk = -c / w;
                if (kk <= 0.f) { a0 += w * u; b0 += c * u; }
                else if (kk < 15.f) { kj[m] = kk; da_[m] = w * u; db_[m] = c * u; m++; }
            } else if (w < 0.f) {
                float kk = -c / w;
                if (kk >= 15.f) { a0 += w * u; b0 += c * u; }
                else if (kk > 0.f) {
                    a0 += w * u; b0 += c * u;
                    kj[m] = kk; da_[m] = -w * u; db_[m] = -c * u; m++;
                }
            } else if (c > 0.f) { b0 += c * u; }
        }
        for (int i = 1; i < m; i++) {
            float kv = kj[i], av = da_[i], bv = db_[i]; int p = i - 1;
            while (p >= 0 && kj[p] > kv) {
                kj[p + 1] = kj[p]; da_[p + 1] = da_[p]; db_[p + 1] = db_[p]; p--;
            }
            kj[p + 1] = kv; da_[p + 1] = av; db_[p + 1] = bv;
        }
        kn[0] = -1e30f; al[0] = a0; be[0] = b0;
        for (int i = 0; i < m; i++) {
            kn[i + 1] = kj[i];
            al[i + 1] = al[i] + da_[i];
            be[i + 1] = be[i] + db_[i];
        }
        for (int i = m + 1; i < 64; i++) kn[i] = 1e30f;
    }

    // ---- Load Q strip (transposed) ----
#pragma unroll
    for (int t = 0; t < 7; t++) {
        int idx = tid + t * 512;
        int m = idx / 28, c4 = (idx % 28) * 4;
        float4 v = *(const float4*)(Qg + (size_t)(rb + m) * NCD + c4);
        Qs[(c4 + 0) * QS_LD + m] = v.x;
        Qs[(c4 + 1) * QS_LD + m] = v.y;
        Qs[(c4 + 2) * QS_LD + m] = v.z;
        Qs[(c4 + 3) * QS_LD + m] = v.w;
    }
    if (tid < FBM) {
        int q = rb + tid;
        cqx[tid] = coords[((size_t)b * NS + q) * 3 + 0];
        cqy[tid] = coords[((size_t)b * NS + q) * 3 + 1];
        cqz[tid] = coords[((size_t)b * NS + q) * 3 + 2];
        qn2s[tid] = g_qn2[bh * NS + q];
    }

    unsigned long long accO[2][7];
#pragma unroll
    for (int t = 0; t < 2; t++)
#pragma unroll
        for (int c = 0; c < 7; c++) accO[t][c] = 0ull;
    float run_m[4], run_s[4];
#pragma unroll
    for (int i = 0; i < 4; i++) { run_m[i] = -1e30f; run_s[i] = 0.f; }

    for (int kb = 0; kb < NS; kb += FBK) {
        __syncthreads();

        // load K (transposed) + V (natural)
#pragma unroll
        for (int t = 0; t < 4; t++) {
            int idx = tid + t * 512;
            if (idx < 1792) {
                int key = idx / 28, c4 = (idx % 28) * 4;
                float4 kv = *(const float4*)(Kg + (size_t)(kb + key) * NCD + c4);
                Ks[(c4 + 0) * KS_LD + key] = kv.x;
                Ks[(c4 + 1) * KS_LD + key] = kv.y;
                Ks[(c4 + 2) * KS_LD + key] = kv.z;
                Ks[(c4 + 3) * KS_LD + key] = kv.w;
                float4 vv = *(const float4*)(Vg + (size_t)(kb + key) * NCD + c4);
                *(float4*)(Vs + key * VS_LD + c4) = vv;
            }
        }
        if (tid < FBK) {
            int kk = kb + tid;
            ckx[tid] = coords[((size_t)b * NS + kk) * 3 + 0];
            cky[tid] = coords[((size_t)b * NS + kk) * 3 + 1];
            ckz[tid] = coords[((size_t)b * NS + kk) * 3 + 2];
            kn2s[tid] = g_kn2[bh * NS + kk];
        }
        __syncthreads();

        // ---- S = Q K^T (128x64), pairs along m ----
        unsigned long long accS[2][4];
#pragma unroll
        for (int t = 0; t < 2; t++)
#pragma unroll
            for (int j = 0; j < 4; j++) accS[t][j] = 0ull;
#pragma unroll 4
        for (int d = 0; d < NCD; d++) {
            float4 qv = *(const float4*)(Qs + d * QS_LD + m0);
            float4 kv = *(const float4*)(Ks + d * KS_LD + n0s);
            unsigned long long a0 = pack2(qv.x, qv.y), a1 = pack2(qv.z, qv.w);
            unsigned long long b0 = dup2(kv.x), b1 = dup2(kv.y), b2 = dup2(kv.z), b3 = dup2(kv.w);
            ffma2(accS[0][0], a0, b0); ffma2(accS[0][1], a0, b1);
            ffma2(accS[0][2], a0, b2); ffma2(accS[0][3], a0, b3);
            ffma2(accS[1][0], a1, b0); ffma2(accS[1][1], a1, b1);
            ffma2(accS[1][2], a1, b2); ffma2(accS[1][3], a1, b3);
        }
        float Sv[4][4];
#pragma unroll
        for (int t = 0; t < 2; t++)
#pragma unroll
            for (int j = 0; j < 4; j++) unpk(accS[t][j], Sv[2 * t][j], Sv[2 * t + 1][j]);

        // ---- bias + mask epilogue ----
#pragma unroll
        for (int i = 0; i < 4; i++) {
            float qx = cqx[m0 + i], qy = cqy[m0 + i], qz = cqz[m0 + i];
            float qn = qn2s[m0 + i];
#pragma unroll
            for (int j = 0; j < 4; j++) {
                int gk = n0s + j;
                float dx = qx - ckx[gk], dy = qy - cky[gk], dz = qz - ckz[gk];
                float d2 = fmaf(dx, dx, fmaf(dy, dy, dz * dz));
                if (d2 < 225.f) {
                    float d = sqrtf(d2);
                    int idx = 0;
#pragma unroll
                    for (int st = 32; st > 0; st >>= 1)
                        if (kn[idx + st] <= d) idx += st;
                    Sv[i][j] += fmaf(al[idx], d, be[idx]) - 0.5f * (qn + kn2s[gk]);
                } else {
                    Sv[i][j] = -1e9f;
                }
            }
        }

        // ---- online softmax (rows shared by 16-lane groups) ----
        float scl[4];
#pragma unroll
        for (int i = 0; i < 4; i++) {
            float mx = fmaxf(fmaxf(Sv[i][0], Sv[i][1]), fmaxf(Sv[i][2], Sv[i][3]));
#pragma unroll
            for (int o = 8; o > 0; o >>= 1) mx = fmaxf(mx, __shfl_xor_sync(0xffffffffu, mx, o));
            float nm = fmaxf(run_m[i], mx);
            float sc = __expf(run_m[i] - nm);
            float ts = 0.f;
#pragma unroll
            for (int j = 0; j < 4; j++) { float p = __expf(Sv[i][j] - nm); Sv[i][j] = p; ts += p; }
#pragma unroll
            for (int o = 8; o > 0; o >>= 1) ts += __shfl_xor_sync(0xffffffffu, ts, o);
            run_s[i] = run_s[i] * sc + ts;
            run_m[i] = nm;
            scl[i] = sc;
        }
        {
            unsigned long long s0 = pack2(scl[0], scl[1]);
            unsigned long long s1 = pack2(scl[2], scl[3]);
#pragma unroll
            for (int c = 0; c < 7; c++) { mul2(accO[0][c], s0); mul2(accO[1][c], s1); }
        }

        // ---- write P (key-major) ----
#pragma unroll
        for (int j = 0; j < 4; j++) {
            float* pp = Ps + (n0s + j) * PS_LD + m0;
            pp[0] = Sv[0][j]; pp[1] = Sv[1][j]; pp[2] = Sv[2][j]; pp[3] = Sv[3][j];
        }
        __syncthreads();

        // ---- O += P * V ----
#pragma unroll 2
        for (int kk = 0; kk < FBK; kk++) {
            const float* pr = Ps + kk * PS_LD + m0;
            const float* vr = Vs + kk * VS_LD + n0o;
            unsigned long long a0 = *(const unsigned long long*)(pr);
            unsigned long long a1 = *(const unsigned long long*)(pr + 2);
#pragma unroll
            for (int c = 0; c < 7; c++) {
                unsigned long long bd = dup2(vr[c]);
                ffma2(accO[0][c], a0, bd);
                ffma2(accO[1][c], a1, bd);
            }
        }
    }

    // ---- finalize: normalize + scatter into concat layout ----
    float inv[4];
#pragma unroll
    for (int i = 0; i < 4; i++) inv[i] = 1.0f / run_s[i];
#pragma unroll
    for (int t = 0; t < 2; t++) {
        int q0 = rb + m0 + 2 * t;
        size_t base0 = (size_t)(b * NS + q0) * ATT_W;
        size_t base1 = base0 + ATT_W;
#pragma unroll
        for (int c = 0; c < 7; c++) {
            int col = n0o + c;
            int cc = (col < 64) ? (h * 64 + col) : (512 + h * 48 + (col - 64));
            float o0, o1; unpk(accO[t][c], o0, o1);
            g_att[base0 + cc] = o0 * inv[2 * t];
            g_att[base1 + cc] = o1 * inv[2 * t + 1];
        }
    }
}

// ---------------- Coords update (block per row) ----------------
__global__ void k_coords(const float* __restrict__ coords, float* __restrict__ outc) {
    int row = blockIdx.x, t = threadIdx.x;   // 128 threads
    const float* ap = g_att + (size_t)row * ATT_W + 512;
    __shared__ float sx[128], sy[128], sz[128];
    sx[t] = ap[t * 3 + 0]; sy[t] = ap[t * 3 + 1]; sz[t] = ap[t * 3 + 2];
    __syncthreads();
    for (int s = 64; s > 0; s >>= 1) {
        if (t < s) { sx[t] += sx[t + s]; sy[t] += sy[t + s]; sz[t] += sz[t + s]; }
        __syncthreads();
    }
    if (t == 0) {
        outc[row * 3 + 0] = coords[row * 3 + 0] + sx[0] * (0.1f / 128.f);
        outc[row * 3 + 1] = coords[row * 3 + 1] + sy[0] * (0.1f / 128.f);
        outc[row * 3 + 2] = coords[row * 3 + 2] + sz[0] * (0.1f / 128.f);
    }
}

// ---------------- Launch ----------------
extern "C" void kernel_launch(void* const* d_in, const int* in_sizes, int n_in,
                              void* d_out, int out_size) {
    const float* x      = (const float*)d_in[0];
    const float* coords = (const float*)d_in[1];
    const float* Wq     = (const float*)d_in[2];
    const float* Wk     = (const float*)d_in[3];
    const float* Wv     = (const float*)d_in[4];
    const float* Wqp    = (const float*)d_in[5];
    const float* bqp    = (const float*)d_in[6];
    const float* Wkp    = (const float*)d_in[7];
    const float* bkp    = (const float*)d_in[8];
    const float* Wvp    = (const float*)d_in[9];
    const float* bvp    = (const float*)d_in[10];
    const float* Wd1    = (const float*)d_in[11];
    const float* bd1    = (const float*)d_in[12];
    const float* Wd2    = (const float*)d_in[13];
    const float* bd2    = (const float*)d_in[14];
    const float* Wo     = (const float*)d_in[15];
    const float* bo     = (const float*)d_in[16];
    const float* g1     = (const float*)d_in[17];
    const float* b1     = (const float*)d_in[18];
    const float* g2     = (const float*)d_in[19];
    const float* b2     = (const float*)d_in[20];
    float* out = (float*)d_out;

    float *p_xn, *p_att, *p_pre;
    cudaGetSymbolAddress((void**)&p_xn,  g_xn);
    cudaGetSymbolAddress((void**)&p_att, g_att);
    cudaGetSymbolAddress((void**)&p_pre, g_pre);

    const int smem_attn = (112 * QS_LD + 112 * KS_LD + 64 * VS_LD + 64 * PS_LD +
                           4 * FBM + 4 * FBK + 64 + 33 + 33) * sizeof(float);
    cudaFuncSetAttribute(k_attn, cudaFuncAttributeMaxDynamicSharedMemorySize, smem_attn);

    // 1. LayerNorm
    k_ln<<<NROWS, 256>>>(x, nullptr, g1, b1, p_xn);
    // 2. Concatenated projection weights + fused projection GEMM with scatter epilogue
    k_wcat<<<(ND * NCAT + 255) / 256, 256>>>(Wq, Wk, Wv, Wqp, Wkp, Wvp);
    k_proj<<<dim3(NCAT / 128, NROWS / 128), 256>>>(coords, bqp, bkp, bvp);
    // 3. Point norms
    k_norms<<<NBH * NS / 8, 256>>>();
    // 4. Fused attention (logits + bias + mask + softmax + AV)
    k_attn<<<dim3(NS / FBM, NBH), 512, smem_attn>>>(coords, Wd1, bd1, Wd2, bd2);
    // 5. Output projection (2048x512x896)
    gemm_nn<4><<<dim3(ND / 128, NROWS / 64), 256>>>(NROWS, ND, ATT_W, p_att, Wo, bo, p_pre);
    // 6. Residual + final LayerNorm -> out
    k_ln<<<NROWS, 256>>>(x, p_pre, g2, b2, out);
    // 7. Coords update -> second output
    k_coords<<<NROWS, 128>>>(coords, out + (size_t)NROWS * ND);
}

// round 6
// speedup vs baseline: 1.5092x; 1.0476x over previous
#include <cuda_runtime.h>
#include <math.h>
#include <stdint.h>

// Problem constants
#define NB 2
#define NS 1024
#define ND 512
#define NH 8
#define NCAT 2688           // 3*512 + 3*384
#define NCD 112             // 64 + 48
#define NBH 16              // NB*NH
#define NROWS 2048          // NB*NS
#define ATT_W 896           // ND + NHP3

// Fused attention tiling
#define FBM 128
#define FBK 64
#define QS_LD 132
#define KS_LD 68
#define VS_LD 116
#define PS_LD 130

// Scratch (static device memory; no runtime allocation)
__device__ float g_xn[NROWS * ND];
__device__ float g_Qc[NBH * NS * NCD];
__device__ float g_Kc[NBH * NS * NCD];
__device__ float g_Vc[NBH * NS * NCD];
__device__ float g_qn2[NBH * NS];
__device__ float g_kn2[NBH * NS];
__device__ float g_att[NROWS * ATT_W];
__device__ float g_pre[NROWS * ND];

// ---------------- f32x2 packed helpers ----------------
__device__ __forceinline__ unsigned long long dup2(float x) {
    unsigned long long r; unsigned u = __float_as_uint(x);
    asm("mov.b64 %0, {%1, %1};" : "=l"(r) : "r"(u));
    return r;
}
__device__ __forceinline__ unsigned long long pack2(float lo, float hi) {
    unsigned long long r;
    asm("mov.b64 %0, {%1, %2};" : "=l"(r) : "r"(__float_as_uint(lo)), "r"(__float_as_uint(hi)));
    return r;
}
__device__ __forceinline__ void ffma2(unsigned long long& c, unsigned long long a, unsigned long long b) {
    asm("fma.rn.f32x2 %0, %1, %2, %0;" : "+l"(c) : "l"(a), "l"(b));
}
__device__ __forceinline__ void mul2(unsigned long long& c, unsigned long long a) {
    asm("mul.rn.f32x2 %0, %0, %1;" : "+l"(c) : "l"(a));
}
__device__ __forceinline__ void unpk(unsigned long long v, float& lo, float& hi) {
    unsigned a, b;
    asm("mov.b64 {%0, %1}, %2;" : "=r"(a), "=r"(b) : "l"(v));
    lo = __uint_as_float(a); hi = __uint_as_float(b);
}
__device__ __forceinline__ void cpasync16(uint32_t dst, const void* src) {
    asm volatile("cp.async.cg.shared.global [%0], [%1], 16;" :: "r"(dst), "l"(src));
}
#define CP_COMMIT() asm volatile("cp.async.commit_group;")
#define CP_WAIT1()  asm volatile("cp.async.wait_group 1;")

// ---------------- LayerNorm (optionally with residual add), shuffle-based ----------------
__global__ void k_ln(const float* __restrict__ x, const float* __restrict__ res,
                     const float* __restrict__ g, const float* __restrict__ b,
                     float* __restrict__ y) {
    int row = blockIdx.x, tid = threadIdx.x;
    const float* xr = x + (size_t)row * ND;
    float v0 = xr[tid], v1 = xr[tid + 256];
    if (res) {
        v0 += res[(size_t)row * ND + tid];
        v1 += res[(size_t)row * ND + tid + 256];
    }
    __shared__ float ws[8], ws2[8];
    float s = v0 + v1;
#pragma unroll
    for (int o = 16; o > 0; o >>= 1) s += __shfl_xor_sync(0xffffffffu, s, o);
    if ((tid & 31) == 0) ws[tid >> 5] = s;
    __syncthreads();
    float tot = ws[0] + ws[1] + ws[2] + ws[3] + ws[4] + ws[5] + ws[6] + ws[7];
    float mean = tot * (1.0f / ND);
    float d0 = v0 - mean, d1 = v1 - mean;
    float s2 = d0 * d0 + d1 * d1;
#pragma unroll
    for (int o = 16; o > 0; o >>= 1) s2 += __shfl_xor_sync(0xffffffffu, s2, o);
    if ((tid & 31) == 0) ws2[tid >> 5] = s2;
    __syncthreads();
    float tv = ws2[0] + ws2[1] + ws2[2] + ws2[3] + ws2[4] + ws2[5] + ws2[6] + ws2[7];
    float rstd = rsqrtf(tv * (1.0f / ND) + 1e-5f);
    float* yr = y + (size_t)row * ND;
    yr[tid]       = d0 * rstd * g[tid] + b[tid];
    yr[tid + 256] = d1 * rstd * g[tid + 256] + b[tid + 256];
}

// ---------------- Scatter element of projection into Qc/Kc/Vc ----------------
__device__ __forceinline__ void scatter_proj(
    int b, int s, int r, int c, float v, const float* __restrict__ coords,
    const float* __restrict__ bqp, const float* __restrict__ bkp, const float* __restrict__ bvp)
{
    if (c < 1536) {
        int seg = c >> 9;
        int cc = c & 511;
        int h = cc >> 6, j = cc & 63;
        size_t o = ((size_t)(b * NH + h) * NS + s) * NCD + j;
        if      (seg == 0) g_Qc[o] = v * 0.125f;   // SCALE = 1/8
        else if (seg == 1) g_Kc[o] = v;
        else               g_Vc[o] = v;
    } else {
        int t = c - 1536;
        int seg = t / 384;
        int cc = t - seg * 384;
        int h = cc / 48, jj = cc - h * 48;
        size_t o = ((size_t)(b * NH + h) * NS + s) * NCD + 64 + jj;
        if      (seg == 0) g_Qc[o] = v + bqp[cc] + coords[r * 3 + jj % 3];
        else if (seg == 1) g_Kc[o] = v + bkp[cc] + coords[r * 3 + jj % 3];
        else               g_Vc[o] = v + bvp[cc];
    }
}

// ---------------- Projection GEMM, direct weight reads, scatter epilogue ----------------
// M=2048, logical N=2688, K=512. BM=BN=128, BK=16, 256 threads, 8x8/thread, f32x2.
__global__ void __launch_bounds__(256, 2)
k_proj(const float* __restrict__ coords,
       const float* __restrict__ Wq, const float* __restrict__ Wk, const float* __restrict__ Wv,
       const float* __restrict__ Wqp, const float* __restrict__ Wkp, const float* __restrict__ Wvp,
       const float* __restrict__ bqp, const float* __restrict__ bkp, const float* __restrict__ bvp)
{
    const float* A = g_xn;
    __shared__ float As[2][16][132];
    __shared__ float Bs[2][16][128];
    const int tid = threadIdx.x;
    const int tn = tid & 15, tm = tid >> 4;
    const int m0 = tm * 8, n0 = tn * 8;
    const int rb = blockIdx.y * 128, cb = blockIdx.x * 128;

    // Segment decode (uniform per CTA; all segment boundaries are multiples of 128)
    const float* W; int ldw, coff;
    if      (cb < 512)  { W = Wq;  ldw = 512; coff = cb; }
    else if (cb < 1024) { W = Wk;  ldw = 512; coff = cb - 512; }
    else if (cb < 1536) { W = Wv;  ldw = 512; coff = cb - 1024; }
    else if (cb < 1920) { W = Wqp; ldw = 384; coff = cb - 1536; }
    else if (cb < 2304) { W = Wkp; ldw = 384; coff = cb - 1920; }
    else                { W = Wvp; ldw = 384; coff = cb - 2304; }

    unsigned long long acc[8][4];
#pragma unroll
    for (int i = 0; i < 8; i++)
#pragma unroll
        for (int j = 0; j < 4; j++) acc[i][j] = 0ull;

    const int aR = tid >> 2, aC = (tid & 3) * 4;
    const int bR = tid >> 5, bC = (tid & 31) * 4;

    float4 av[2], bv[2];
#pragma unroll
    for (int i = 0; i < 2; i++) {
        av[i] = *(const float4*)(A + (size_t)(rb + aR + i * 64) * ND + aC);
        bv[i] = *(const float4*)(W + (size_t)(bR + i * 8) * ldw + coff + bC);
    }
#pragma unroll
    for (int i = 0; i < 2; i++) {
        As[0][aC + 0][aR + i * 64] = av[i].x; As[0][aC + 1][aR + i * 64] = av[i].y;
        As[0][aC + 2][aR + i * 64] = av[i].z; As[0][aC + 3][aR + i * 64] = av[i].w;
        *(float4*)&Bs[0][bR + i * 8][bC] = bv[i];
    }
    __syncthreads();

    int buf = 0;
    for (int k0 = 0; k0 < ND; k0 += 16) {
        const bool nxt = (k0 + 16) < ND;
        if (nxt) {
#pragma unroll
            for (int i = 0; i < 2; i++) {
                av[i] = *(const float4*)(A + (size_t)(rb + aR + i * 64) * ND + k0 + 16 + aC);
                bv[i] = *(const float4*)(W + (size_t)(k0 + 16 + bR + i * 8) * ldw + coff + bC);
            }
        }
#pragma unroll
        for (int kk = 0; kk < 16; kk++) {
            unsigned long long bb[4], ad[8];
#pragma unroll
            for (int j = 0; j < 4; j++)
                bb[j] = *(const unsigned long long*)&Bs[buf][kk][n0 + 2 * j];
#pragma unroll
            for (int i = 0; i < 8; i++)
                ad[i] = dup2(As[buf][kk][m0 + i]);
#pragma unroll
            for (int i = 0; i < 8; i++)
#pragma unroll
                for (int j = 0; j < 4; j++)
                    ffma2(acc[i][j], ad[i], bb[j]);
        }
        if (nxt) {
            int nb = buf ^ 1;
#pragma unroll
            for (int i = 0; i < 2; i++) {
                As[nb][aC + 0][aR + i * 64] = av[i].x; As[nb][aC + 1][aR + i * 64] = av[i].y;
                As[nb][aC + 2][aR + i * 64] = av[i].z; As[nb][aC + 3][aR + i * 64] = av[i].w;
                *(float4*)&Bs[nb][bR + i * 8][bC] = bv[i];
            }
            __syncthreads();
            buf = nb;
        }
    }

#pragma unroll
    for (int i = 0; i < 8; i++) {
        int r = rb + m0 + i;
        int b = r >> 10, s = r & 1023;
#pragma unroll
        for (int j = 0; j < 4; j++) {
            int c = cb + n0 + 2 * j;
            float lo, hi; unpk(acc[i][j], lo, hi);
            scatter_proj(b, s, r, c,     lo, coords, bqp, bkp, bvp);
            scatter_proj(b, s, r, c + 1, hi, coords, bqp, bkp, bvp);
        }
    }
}

// ---------------- NN SGEMM (output projection): C = A @ B + bias ----------------
template<int TM>
__global__ void __launch_bounds__(256, 2)
gemm_nn(int M, int N, int K,
        const float* __restrict__ A, const float* __restrict__ B,
        const float* __restrict__ bias, float* __restrict__ C)
{
    constexpr int BM = TM * 16;
    constexpr int AP = BM + 4;
    constexpr int LA = BM / 64;
    __shared__ float As[2][16][AP];
    __shared__ float Bs[2][16][128];
    const int tid = threadIdx.x;
    const int tn = tid & 15, tm = tid >> 4;
    const int m0 = tm * TM, n0 = tn * 8;
    const int rb = blockIdx.y * BM, cb = blockIdx.x * 128;

    unsigned long long acc[TM][4];
#pragma unroll
    for (int i = 0; i < TM; i++)
#pragma unroll
        for (int j = 0; j < 4; j++) acc[i][j] = 0ull;

    int aR[LA], aC[LA];
#pragma unroll
    for (int i = 0; i < LA; i++) { int idx = tid + i * 256; aR[i] = idx >> 2; aC[i] = (idx & 3) * 4; }
    int bR[2], bC[2];
#pragma unroll
    for (int i = 0; i < 2; i++)  { int idx = tid + i * 256; bR[i] = idx >> 5; bC[i] = (idx & 31) * 4; }

    float4 av[LA], bv[2];
#pragma unroll
    for (int i = 0; i < LA; i++)
        av[i] = *(const float4*)(A + (size_t)(rb + aR[i]) * K + aC[i]);
#pragma unroll
    for (int i = 0; i < 2; i++) {
        int col = cb + bC[i];
        bv[i] = (col < N) ? *(const float4*)(B + (size_t)bR[i] * N + col)
                          : make_float4(0.f, 0.f, 0.f, 0.f);
    }
#pragma unroll
    for (int i = 0; i < LA; i++) {
        As[0][aC[i] + 0][aR[i]] = av[i].x;
        As[0][aC[i] + 1][aR[i]] = av[i].y;
        As[0][aC[i] + 2][aR[i]] = av[i].z;
        As[0][aC[i] + 3][aR[i]] = av[i].w;
    }
#pragma unroll
    for (int i = 0; i < 2; i++)
        *(float4*)&Bs[0][bR[i]][bC[i]] = bv[i];
    __syncthreads();

    int buf = 0;
    for (int k0 = 0; k0 < K; k0 += 16) {
        const bool nxt = (k0 + 16) < K;
        if (nxt) {
#pragma unroll
            for (int i = 0; i < LA; i++)
                av[i] = *(const float4*)(A + (size_t)(rb + aR[i]) * K + k0 + 16 + aC[i]);
#pragma unroll
            for (int i = 0; i < 2; i++) {
                int col = cb + bC[i];
                bv[i] = (col < N) ? *(const float4*)(B + (size_t)(k0 + 16 + bR[i]) * N + col)
                                  : make_float4(0.f, 0.f, 0.f, 0.f);
            }
        }
#pragma unroll
        for (int kk = 0; kk < 16; kk++) {
            unsigned long long bb[4], ad[TM];
#pragma unroll
            for (int j = 0; j < 4; j++)
                bb[j] = *(const unsigned long long*)&Bs[buf][kk][n0 + 2 * j];
#pragma unroll
            for (int i = 0; i < TM; i++)
                ad[i] = dup2(As[buf][kk][m0 + i]);
#pragma unroll
            for (int i = 0; i < TM; i++)
#pragma unroll
                for (int j = 0; j < 4; j++)
                    ffma2(acc[i][j], ad[i], bb[j]);
        }
        if (nxt) {
            int nb = buf ^ 1;
#pragma unroll
            for (int i = 0; i < LA; i++) {
                As[nb][aC[i] + 0][aR[i]] = av[i].x;
                As[nb][aC[i] + 1][aR[i]] = av[i].y;
                As[nb][aC[i] + 2][aR[i]] = av[i].z;
                As[nb][aC[i] + 3][aR[i]] = av[i].w;
            }
#pragma unroll
            for (int i = 0; i < 2; i++)
                *(float4*)&Bs[nb][bR[i]][bC[i]] = bv[i];
            __syncthreads();
            buf = nb;
        }
    }

#pragma unroll
    for (int i = 0; i < TM; i++) {
        int r = rb + m0 + i;
#pragma unroll
        for (int j = 0; j < 4; j++) {
            int c = cb + n0 + 2 * j;
            if (c >= N) continue;
            float lo, hi; unpk(acc[i][j], lo, hi);
            if (bias) { lo += bias[c]; hi += bias[c + 1]; }
            C[(size_t)r * N + c]     = lo;
            C[(size_t)r * N + c + 1] = hi;
        }
    }
}

// ---------------- Point norms ----------------
__global__ void k_norms() {
    int t = threadIdx.x;
    int r = blockIdx.x * 8 + (t >> 5);
    int lane = t & 31;
    const float* q = g_Qc + (size_t)r * NCD + 64;
    const float* k = g_Kc + (size_t)r * NCD + 64;
    float qa = q[lane], ka = k[lane];
    float qb = 0.f, kb = 0.f;
    if (lane < 16) { qb = q[32 + lane]; kb = k[32 + lane]; }
    float qs = qa * qa + qb * qb;
    float ks = ka * ka + kb * kb;
#pragma unroll
    for (int o = 16; o > 0; o >>= 1) {
        qs += __shfl_xor_sync(0xffffffffu, qs, o);
        ks += __shfl_xor_sync(0xffffffffu, ks, o);
    }
    if (lane == 0) { g_qn2[r] = qs; g_kn2[r] = ks; }
}

// ---------------- Fused attention, pipelined; ROW-WIDE shared max softmax ----------------
// 512 threads, 32x16 grid; per thread: 4 rows x (4 S-cols / 7 O-cols).
// Softmax max is reduced across the 16-lane row group every tile (required so the
// shared Ps tile entries are all relative to ONE row max); partial sums stay
// per-thread and merge once at the end.
__global__ void __launch_bounds__(512, 1)
k_attn(const float* __restrict__ coords,
       const float* __restrict__ Wd1, const float* __restrict__ bd1,
       const float* __restrict__ Wd2, const float* __restrict__ bd2)
{
    extern __shared__ float smp[];
    float* Qs   = smp;                    // [112][132] transposed
    float* Ks   = Qs + 112 * QS_LD;       // [112][68]  transposed
    float* Vs0  = Ks + 112 * KS_LD;       // [2][64][116] natural, double buffered
    float* Ps   = Vs0 + 2 * 64 * VS_LD;   // [64][130]  key-major
    float* cqx  = Ps + 64 * PS_LD;
    float* cqy  = cqx + FBM;
    float* cqz  = cqy + FBM;
    float* qn2s = cqz + FBM;
    float* ckx  = qn2s + FBM;
    float* cky  = ckx + FBK;
    float* ckz  = cky + FBK;
    float* kn2s = ckz + FBK;
    float* kn   = kn2s + FBK;             // [64] knot table
    float* al   = kn + 64;                // [33]
    float* be   = al + 33;                // [33]

    const int bh = blockIdx.y;
    const int b  = bh >> 3, h = bh & 7;
    const int rb = blockIdx.x * FBM;
    const int tid = threadIdx.x;
    const int tm = tid >> 4, tn = tid & 15;   // 32 x 16
    const int m0 = tm * 4, n0s = tn * 4, n0o = tn * 7;

    const float* Qg = g_Qc + (size_t)bh * NS * NCD;
    const float* Kg = g_Kc + (size_t)bh * NS * NCD;
    const float* Vg = g_Vc + (size_t)bh * NS * NCD;

    // Loader geometry: 1792 float4 per K/V tile
    const int lKey[4] = { (tid) / 28, (tid + 512) / 28, (tid + 1024) / 28, (tid + 1536) / 28 };
    const int lC4[4]  = { ((tid) % 28) * 4, ((tid + 512) % 28) * 4,
                          ((tid + 1024) % 28) * 4, ((tid + 1536) % 28) * 4 };
    const bool lOk3 = (tid + 1536) < 1792;

    // ---- Exact piecewise-linear LUT for hbias_h(d) on (0,15) ----
    if (tid == 0) {
        float kj[32], da_[32], db_[32];
        int m = 0;
        float a0 = 0.f, b0 = bd2[h];
        for (int j = 0; j < 32; j++) {
            float w = Wd1[j], c = bd1[j], u = Wd2[j * 8 + h];
            if (w > 0.f) {
                float kk = -c / w;
                if (kk <= 0.f) { a0 += w * u; b0 += c * u; }
                else if (kk < 15.f) { kj[m] = kk; da_[m] = w * u; db_[m] = c * u; m++; }
            } else if (w < 0.f) {
                float kk = -c / w;
                if (kk >= 15.f) { a0 += w * u; b0 += c * u; }
                else if (kk > 0.f) {
                    a0 += w * u; b0 += c * u;
                    kj[m] = kk; da_[m] = -w * u; db_[m] = -c * u; m++;
                }
            } else if (c > 0.f) { b0 += c * u; }
        }
        for (int i = 1; i < m; i++) {
            float kv = kj[i], av = da_[i], bv = db_[i]; int p = i - 1;
            while (p >= 0 && kj[p] > kv) {
                kj[p + 1] = kj[p]; da_[p + 1] = da_[p]; db_[p + 1] = db_[p]; p--;
            }
            kj[p + 1] = kv; da_[p + 1] = av; db_[p + 1] = bv;
        }
        kn[0] = -1e30f; al[0] = a0; be[0] = b0;
        for (int i = 0; i < m; i++) {
            kn[i + 1] = kj[i];
            al[i + 1] = al[i] + da_[i];
            be[i + 1] = be[i] + db_[i];
        }
        for (int i = m + 1; i < 64; i++) kn[i] = 1e30f;
    }

    // ---- Load Q strip (transposed) + q-side per-row data ----
#pragma unroll
    for (int t = 0; t < 7; t++) {
        int idx = tid + t * 512;
        int m = idx / 28, c4 = (idx % 28) * 4;
        float4 v = *(const float4*)(Qg + (size_t)(rb + m) * NCD + c4);
        Qs[(c4 + 0) * QS_LD + m] = v.x;
        Qs[(c4 + 1) * QS_LD + m] = v.y;
        Qs[(c4 + 2) * QS_LD + m] = v.z;
        Qs[(c4 + 3) * QS_LD + m] = v.w;
    }
    if (tid < FBM) {
        int q = rb + tid;
        cqx[tid] = coords[((size_t)b * NS + q) * 3 + 0];
        cqy[tid] = coords[((size_t)b * NS + q) * 3 + 1];
        cqz[tid] = coords[((size_t)b * NS + q) * 3 + 2];
        qn2s[tid] = g_qn2[bh * NS + q];
    }

    // ---- Preload tile 0: K into regs, V via cp.async into Vs buf0, k-side scalars ----
    float4 kreg[4];
    float crx = 0.f, cry = 0.f, crz = 0.f, crn = 0.f;
#pragma unroll
    for (int t = 0; t < 4; t++) {
        if (t < 3 || lOk3) {
            kreg[t] = *(const float4*)(Kg + (size_t)lKey[t] * NCD + lC4[t]);
            uint32_t dst = (uint32_t)__cvta_generic_to_shared(Vs0 + lKey[t] * VS_LD + lC4[t]);
            cpasync16(dst, Vg + (size_t)lKey[t] * NCD + lC4[t]);
        }
    }
    CP_COMMIT();
    if (tid < FBK) {
        crx = coords[((size_t)b * NS + tid) * 3 + 0];
        cry = coords[((size_t)b * NS + tid) * 3 + 1];
        crz = coords[((size_t)b * NS + tid) * 3 + 2];
        crn = g_kn2[bh * NS + tid];
    }

    unsigned long long accO[2][7];
#pragma unroll
    for (int t = 0; t < 2; t++)
#pragma unroll
        for (int c = 0; c < 7; c++) accO[t][c] = 0ull;
    float run_m[4], run_s[4];   // run_m is ROW-WIDE (identical across the 16-lane group)
#pragma unroll
    for (int i = 0; i < 4; i++) { run_m[i] = -1e30f; run_s[i] = 0.f; }

    int buf = 0;
    for (int kb = 0; kb < NS; kb += FBK) {
        // Store prefetched K regs + k-side scalars (prior PV reads only Ps/Vs — no race)
#pragma unroll
        for (int t = 0; t < 4; t++) {
            if (t < 3 || lOk3) {
                int key = lKey[t], c4 = lC4[t];
                Ks[(c4 + 0) * KS_LD + key] = kreg[t].x;
                Ks[(c4 + 1) * KS_LD + key] = kreg[t].y;
                Ks[(c4 + 2) * KS_LD + key] = kreg[t].z;
                Ks[(c4 + 3) * KS_LD + key] = kreg[t].w;
            }
        }
        if (tid < FBK) { ckx[tid] = crx; cky[tid] = cry; ckz[tid] = crz; kn2s[tid] = crn; }
        __syncthreads();

        // ---- S = Q K^T (128x64), pairs along m ----
        unsigned long long accS[2][4];
#pragma unroll
        for (int t = 0; t < 2; t++)
#pragma unroll
            for (int j = 0; j < 4; j++) accS[t][j] = 0ull;
#pragma unroll 4
        for (int d = 0; d < NCD; d++) {
            float4 qv = *(const float4*)(Qs + d * QS_LD + m0);
            float4 kv = *(const float4*)(Ks + d * KS_LD + n0s);
            unsigned long long a0 = pack2(qv.x, qv.y), a1 = pack2(qv.z, qv.w);
            unsigned long long b0 = dup2(kv.x), b1 = dup2(kv.y), b2 = dup2(kv.z), b3 = dup2(kv.w);
            ffma2(accS[0][0], a0, b0); ffma2(accS[0][1], a0, b1);
            ffma2(accS[0][2], a0, b2); ffma2(accS[0][3], a0, b3);
            ffma2(accS[1][0], a1, b0); ffma2(accS[1][1], a1, b1);
            ffma2(accS[1][2], a1, b2); ffma2(accS[1][3], a1, b3);
        }

        // ---- Prefetch next tile: K regs + V cp.async into other buffer ----
        const int kb2 = kb + FBK;
        if (kb2 < NS) {
            float* Vnext = Vs0 + (buf ^ 1) * 64 * VS_LD;
#pragma unroll
            for (int t = 0; t < 4; t++) {
                if (t < 3 || lOk3) {
                    kreg[t] = *(const float4*)(Kg + (size_t)(kb2 + lKey[t]) * NCD + lC4[t]);
                    uint32_t dst = (uint32_t)__cvta_generic_to_shared(Vnext + lKey[t] * VS_LD + lC4[t]);
                    cpasync16(dst, Vg + (size_t)(kb2 + lKey[t]) * NCD + lC4[t]);
                }
            }
            if (tid < FBK) {
                crx = coords[((size_t)b * NS + kb2 + tid) * 3 + 0];
                cry = coords[((size_t)b * NS + kb2 + tid) * 3 + 1];
                crz = coords[((size_t)b * NS + kb2 + tid) * 3 + 2];
                crn = g_kn2[bh * NS + kb2 + tid];
            }
        }
        CP_COMMIT();

        float Sv[4][4];
#pragma unroll
        for (int t = 0; t < 2; t++)
#pragma unroll
            for (int j = 0; j < 4; j++) unpk(accS[t][j], Sv[2 * t][j], Sv[2 * t + 1][j]);

        // ---- bias + mask epilogue (branch-free) ----
#pragma unroll
        for (int i = 0; i < 4; i++) {
            float qx = cqx[m0 + i], qy = cqy[m0 + i], qz = cqz[m0 + i];
            float qn = qn2s[m0 + i];
#pragma unroll
            for (int j = 0; j < 4; j++) {
                int gk = n0s + j;
                float dx = qx - ckx[gk], dy = qy - cky[gk], dz = qz - ckz[gk];
                float d2 = fmaf(dx, dx, fmaf(dy, dy, dz * dz));
                float d = sqrtf(d2);
                int idx = 0;
#pragma unroll
                for (int st = 32; st > 0; st >>= 1)
                    if (kn[idx + st] <= d) idx += st;
                float bias = fmaf(al[idx], d, be[idx]) - 0.5f * (qn + kn2s[gk]);
                Sv[i][j] = (d2 < 225.f) ? Sv[i][j] + bias : -1e9f;
            }
        }

        // ---- online softmax: ROW-WIDE max (16-lane shuffle), per-thread partial sum ----
        float scl[4];
#pragma unroll
        for (int i = 0; i < 4; i++) {
            float mx = fmaxf(fmaxf(Sv[i][0], Sv[i][1]), fmaxf(Sv[i][2], Sv[i][3]));
#pragma unroll
            for (int o = 8; o > 0; o >>= 1) mx = fmaxf(mx, __shfl_xor_sync(0xffffffffu, mx, o));
            float nm = fmaxf(run_m[i], mx);           // identical across the row group
            float sc = __expf(run_m[i] - nm);
            float ts = 0.f;
#pragma unroll
            for (int j = 0; j < 4; j++) { float p = __expf(Sv[i][j] - nm); Sv[i][j] = p; ts += p; }
            run_s[i] = run_s[i] * sc + ts;            // per-thread partial (shared max)
            run_m[i] = nm;
            scl[i] = sc;
        }
        {
            unsigned long long s0 = pack2(scl[0], scl[1]);
            unsigned long long s1 = pack2(scl[2], scl[3]);
#pragma unroll
            for (int c = 0; c < 7; c++) { mul2(accO[0][c], s0); mul2(accO[1][c], s1); }
        }

        // ---- write P (key-major; all entries relative to the shared row max) ----
#pragma unroll
        for (int j = 0; j < 4; j++) {
            float* pp = Ps + (n0s + j) * PS_LD + m0;
            pp[0] = Sv[0][j]; pp[1] = Sv[1][j]; pp[2] = Sv[2][j]; pp[3] = Sv[3][j];
        }
        CP_WAIT1();        // V(current) resident; V(next) may still fly
        __syncthreads();   // Ps visible to all

        // ---- O += P * V ----
        const float* Vs = Vs0 + buf * 64 * VS_LD;
#pragma unroll 2
        for (int kk = 0; kk < FBK; kk++) {
            const float* pr = Ps + kk * PS_LD + m0;
            const float* vr = Vs + kk * VS_LD + n0o;
            unsigned long long a0 = *(const unsigned long long*)(pr);
            unsigned long long a1 = *(const unsigned long long*)(pr + 2);
#pragma unroll
            for (int c = 0; c < 7; c++) {
                unsigned long long bd = dup2(vr[c]);
                ffma2(accO[0][c], a0, bd);
                ffma2(accO[1][c], a1, bd);
            }
        }
        buf ^= 1;
    }

    // ---- final: merge per-thread partial sums (max already shared) + scatter ----
    float fac[4];
#pragma unroll
    for (int i = 0; i < 4; i++) {
        float s = run_s[i];
#pragma unroll
        for (int o = 8; o > 0; o >>= 1) s += __shfl_xor_sync(0xffffffffu, s, o);
        fac[i] = 1.0f / s;
    }
#pragma unroll
    for (int t = 0; t < 2; t++) {
        int q0 = rb + m0 + 2 * t;
        size_t base0 = (size_t)(b * NS + q0) * ATT_W;
        size_t base1 = base0 + ATT_W;
#pragma unroll
        for (int c = 0; c < 7; c++) {
            int col = n0o + c;
            int cc = (col < 64) ? (h * 64 + col) : (512 + h * 48 + (col - 64));
            float o0, o1; unpk(accO[t][c], o0, o1);
            g_att[base0 + cc] = o0 * fac[2 * t];
            g_att[base1 + cc] = o1 * fac[2 * t + 1];
        }
    }
}

// ---------------- Coords update (block per row) ----------------
__global__ void k_coords(const float* __restrict__ coords, float* __restrict__ outc) {
    int row = blockIdx.x, t = threadIdx.x;   // 128 threads
    const float* ap = g_att + (size_t)row * ATT_W + 512;
    __shared__ float sx[128], sy[128], sz[128];
    sx[t] = ap[t * 3 + 0]; sy[t] = ap[t * 3 + 1]; sz[t] = ap[t * 3 + 2];
    __syncthreads();
    for (int s = 64; s > 0; s >>= 1) {
        if (t < s) { sx[t] += sx[t + s]; sy[t] += sy[t + s]; sz[t] += sz[t + s]; }
        __syncthreads();
    }
    if (t == 0) {
        outc[row * 3 + 0] = coords[row * 3 + 0] + sx[0] * (0.1f / 128.f);
        outc[row * 3 + 1] = coords[row * 3 + 1] + sy[0] * (0.1f / 128.f);
        outc[row * 3 + 2] = coords[row * 3 + 2] + sz[0] * (0.1f / 128.f);
    }
}

// ---------------- Launch ----------------
extern "C" void kernel_launch(void* const* d_in, const int* in_sizes, int n_in,
                              void* d_out, int out_size) {
    const float* x      = (const float*)d_in[0];
    const float* coords = (const float*)d_in[1];
    const float* Wq     = (const float*)d_in[2];
    const float* Wk     = (const float*)d_in[3];
    const float* Wv     = (const float*)d_in[4];
    const float* Wqp    = (const float*)d_in[5];
    const float* bqp    = (const float*)d_in[6];
    const float* Wkp    = (const float*)d_in[7];
    const float* bkp    = (const float*)d_in[8];
    const float* Wvp    = (const float*)d_in[9];
    const float* bvp    = (const float*)d_in[10];
    const float* Wd1    = (const float*)d_in[11];
    const float* bd1    = (const float*)d_in[12];
    const float* Wd2    = (const float*)d_in[13];
    const float* bd2    = (const float*)d_in[14];
    const float* Wo     = (const float*)d_in[15];
    const float* bo     = (const float*)d_in[16];
    const float* g1     = (const float*)d_in[17];
    const float* b1     = (const float*)d_in[18];
    const float* g2     = (const float*)d_in[19];
    const float* b2     = (const float*)d_in[20];
    float* out = (float*)d_out;

    float *p_xn, *p_att, *p_pre;
    cudaGetSymbolAddress((void**)&p_xn,  g_xn);
    cudaGetSymbolAddress((void**)&p_att, g_att);
    cudaGetSymbolAddress((void**)&p_pre, g_pre);

    const int smem_attn = (112 * QS_LD + 112 * KS_LD + 2 * 64 * VS_LD + 64 * PS_LD +
                           4 * FBM + 4 * FBK + 64 + 33 + 33) * sizeof(float);
    cudaFuncSetAttribute(k_attn, cudaFuncAttributeMaxDynamicSharedMemorySize, smem_attn);

    // 1. LayerNorm
    k_ln<<<NROWS, 256>>>(x, nullptr, g1, b1, p_xn);
    // 2. Projection GEMM (direct weight reads) with scatter epilogue
    k_proj<<<dim3(NCAT / 128, NROWS / 128), 256>>>(coords, Wq, Wk, Wv, Wqp, Wkp, Wvp,
                                                   bqp, bkp, bvp);
    // 3. Point norms
    k_norms<<<NBH * NS / 8, 256>>>();
    // 4. Fused attention (logits + bias + mask + softmax + AV), pipelined
    k_attn<<<dim3(NS / FBM, NBH), 512, smem_attn>>>(coords, Wd1, bd1, Wd2, bd2);
    // 5. Output projection (2048x512x896)
    gemm_nn<4><<<dim3(ND / 128, NROWS / 64), 256>>>(NROWS, ND, ATT_W, p_att, Wo, bo, p_pre);
    // 6. Residual + final LayerNorm -> out
    k_ln<<<NROWS, 256>>>(x, p_pre, g2, b2, out);
    // 7. Coords update -> second output
    k_coords<<<NROWS, 128>>>(coords, out + (size_t)NROWS * ND);
}